// round 1
// baseline (speedup 1.0000x reference)
#include <cuda_runtime.h>
#include <cstddef>

// ---------------------------------------------------------------------------
// GPT2Attention: B=4, S=2048, D=1024, HD=128, causal single-head.
//   q = x @ Wq ; k = x @ Wk ; v = x @ Wv           (fp32 GEMMs)
//   out = softmax(mask(q k^T / sqrt(HD))) @ v      (flash-attention, fp32)
// ---------------------------------------------------------------------------

#define BATCH 4
#define SEQ   2048
#define DIM   1024
#define HD    128
#define BS    (BATCH * SEQ)     // 8192 rows

// Scratch for projections (device globals: allocation-free per harness rules)
__device__ float g_q[(size_t)BS * HD];
__device__ float g_k[(size_t)BS * HD];
__device__ float g_v[(size_t)BS * HD];

// ===========================================================================
// Kernel 1: QKV projection GEMM. C[8192,128] = x[8192,1024] @ W[1024,128]
// BM=128, BN=128 (full N), BK=16, 256 threads, 8x8 per thread (4+4 split).
// grid = (64, 3): blockIdx.y selects (Wq,Wk,Wv) -> (g_q,g_k,g_v).
// ===========================================================================
__global__ void __launch_bounds__(256, 2)
qkv_gemm_kernel(const float* __restrict__ x,
                const float* __restrict__ Wq,
                const float* __restrict__ Wk,
                const float* __restrict__ Wv)
{
    __shared__ __align__(16) float As[16][132];   // A tile, transposed [k][m]
    __shared__ __align__(16) float Bs[16][132];   // B tile [k][n]

    const float* W  = (blockIdx.y == 0) ? Wq : (blockIdx.y == 1) ? Wk : Wv;
    float*       out = (blockIdx.y == 0) ? g_q : (blockIdx.y == 1) ? g_k : g_v;

    const int m0  = blockIdx.x * 128;
    const int tid = threadIdx.x;
    const int ty  = tid >> 4;        // 0..15 -> row groups
    const int tx  = tid & 15;        // 0..15 -> col groups

    // global loaders
    const int arow = tid >> 2;       // 0..63
    const int ac4  = tid & 3;        // 0..3  (16 floats per A row)
    const int brow = tid >> 5;       // 0..7
    const int bc4  = tid & 31;       // 0..31 (128 floats per B row)

    float acc[8][8];
#pragma unroll
    for (int i = 0; i < 8; i++)
#pragma unroll
        for (int j = 0; j < 8; j++) acc[i][j] = 0.f;

    for (int k0 = 0; k0 < DIM; k0 += 16) {
        // fetch A (128x16) and B (16x128) tiles into registers
        float4 a0 = *(const float4*)&x[(size_t)(m0 + arow)      * DIM + k0 + ac4 * 4];
        float4 a1 = *(const float4*)&x[(size_t)(m0 + 64 + arow) * DIM + k0 + ac4 * 4];
        float4 b0 = *(const float4*)&W[(size_t)(k0 + brow)     * HD + bc4 * 4];
        float4 b1 = *(const float4*)&W[(size_t)(k0 + 8 + brow) * HD + bc4 * 4];

        __syncthreads();   // protect previous tile's smem reads
        As[ac4 * 4 + 0][arow]      = a0.x;
        As[ac4 * 4 + 1][arow]      = a0.y;
        As[ac4 * 4 + 2][arow]      = a0.z;
        As[ac4 * 4 + 3][arow]      = a0.w;
        As[ac4 * 4 + 0][64 + arow] = a1.x;
        As[ac4 * 4 + 1][64 + arow] = a1.y;
        As[ac4 * 4 + 2][64 + arow] = a1.z;
        As[ac4 * 4 + 3][64 + arow] = a1.w;
        *(float4*)&Bs[brow][bc4 * 4]     = b0;
        *(float4*)&Bs[brow + 8][bc4 * 4] = b1;
        __syncthreads();

#pragma unroll
        for (int kk = 0; kk < 16; kk++) {
            float4 av0 = *(const float4*)&As[kk][ty * 4];
            float4 av1 = *(const float4*)&As[kk][64 + ty * 4];
            float4 bv0 = *(const float4*)&Bs[kk][tx * 4];
            float4 bv1 = *(const float4*)&Bs[kk][64 + tx * 4];
            float a[8] = {av0.x, av0.y, av0.z, av0.w, av1.x, av1.y, av1.z, av1.w};
            float b[8] = {bv0.x, bv0.y, bv0.z, bv0.w, bv1.x, bv1.y, bv1.z, bv1.w};
#pragma unroll
            for (int i = 0; i < 8; i++)
#pragma unroll
                for (int j = 0; j < 8; j++) acc[i][j] += a[i] * b[j];
        }
    }

    // epilogue: rows m0 + {ty*4+i, 64+ty*4+i}; cols {tx*4+j, 64+tx*4+j}
#pragma unroll
    for (int ih = 0; ih < 2; ih++) {
#pragma unroll
        for (int i = 0; i < 4; i++) {
            int r = m0 + ih * 64 + ty * 4 + i;
            float4 o0 = make_float4(acc[ih * 4 + i][0], acc[ih * 4 + i][1],
                                    acc[ih * 4 + i][2], acc[ih * 4 + i][3]);
            float4 o1 = make_float4(acc[ih * 4 + i][4], acc[ih * 4 + i][5],
                                    acc[ih * 4 + i][6], acc[ih * 4 + i][7]);
            *(float4*)&out[(size_t)r * HD + tx * 4]      = o0;
            *(float4*)&out[(size_t)r * HD + 64 + tx * 4] = o1;
        }
    }
}

// ===========================================================================
// Kernel 2: causal flash attention, fp32.
// BQ=32 q-rows per tile, BKT=64 k-rows per tile, 128 threads.
// Each block handles the q-tile PAIR (p, 63-p) -> balanced 33-34 k-tiles.
// grid = (32 pairs, 4 batches) = 128 blocks = 1 wave.
// ===========================================================================
#define QPITCH 132
#define SPITCH 68
#define SOFTMAX_SCALE 0.088388347648318447f   // 1/sqrt(128)
// smem floats: Q 32*132, K 64*132, V 64*132, S 32*68, M/L/C 32 each
#define SM_Q   0
#define SM_K   (32 * QPITCH)                       // 4224
#define SM_V   (SM_K + 64 * QPITCH)                // 12672
#define SM_S   (SM_V + 64 * QPITCH)                // 21120
#define SM_M   (SM_S + 32 * SPITCH)                // 23296
#define SM_L   (SM_M + 32)
#define SM_C   (SM_L + 32)
#define SMEM_ATTN_FLOATS (SM_C + 32)               // 23392 floats
#define SMEM_ATTN_BYTES  (SMEM_ATTN_FLOATS * 4)    // 93568 B

__global__ void __launch_bounds__(128, 1)
flash_attn_kernel(float* __restrict__ out)
{
    extern __shared__ __align__(16) float sm[];
    float* Qs = sm + SM_Q;
    float* Ks = sm + SM_K;
    float* Vs = sm + SM_V;
    float* Ss = sm + SM_S;
    float* Ms = sm + SM_M;
    float* Ls = sm + SM_L;
    float* Cs = sm + SM_C;

    const int b   = blockIdx.y;
    const int tid = threadIdx.x;
    const int ty  = tid >> 4;   // 0..7   (row group: rows ty + 8*i)
    const int tx  = tid & 15;   // 0..15

    const float* Qg = g_q + (size_t)b * SEQ * HD;
    const float* Kg = g_k + (size_t)b * SEQ * HD;
    const float* Vg = g_v + (size_t)b * SEQ * HD;

    for (int half = 0; half < 2; half++) {
        const int p  = half ? (63 - (int)blockIdx.x) : (int)blockIdx.x;
        const int q0 = p * 32;

        __syncthreads();   // protect smem from previous half

        // load Q tile: 32 rows x 128 cols
        for (int i = tid; i < 32 * 32; i += 128) {
            int r = i >> 5, c = (i & 31) * 4;
            *(float4*)&Qs[r * QPITCH + c] =
                *(const float4*)&Qg[(size_t)(q0 + r) * HD + c];
        }
        if (tid < 32) { Ms[tid] = -1e30f; Ls[tid] = 0.f; }

        float acc[4][8];
#pragma unroll
        for (int i = 0; i < 4; i++)
#pragma unroll
            for (int j = 0; j < 8; j++) acc[i][j] = 0.f;

        const int nkt = q0 / 64 + 1;
        for (int kt = 0; kt < nkt; kt++) {
            const int k0 = kt * 64;
            __syncthreads();   // previous tile's phase C done
            // load K, V tiles: 64 rows x 128 cols each
            for (int i = tid; i < 64 * 32; i += 128) {
                int r = i >> 5, c = (i & 31) * 4;
                *(float4*)&Ks[r * QPITCH + c] =
                    *(const float4*)&Kg[(size_t)(k0 + r) * HD + c];
                *(float4*)&Vs[r * QPITCH + c] =
                    *(const float4*)&Vg[(size_t)(k0 + r) * HD + c];
            }
            __syncthreads();

            // ---- phase A: S = Q K^T (scaled, causal-masked) ----
            // thread owns rows {ty+8i}, cols {tx+16j}
            float s[4][4];
#pragma unroll
            for (int i = 0; i < 4; i++)
#pragma unroll
                for (int j = 0; j < 4; j++) s[i][j] = 0.f;

#pragma unroll 8
            for (int d = 0; d < HD; d += 4) {
                float4 qv[4], kv[4];
#pragma unroll
                for (int i = 0; i < 4; i++)
                    qv[i] = *(const float4*)&Qs[(ty + 8 * i) * QPITCH + d];
#pragma unroll
                for (int j = 0; j < 4; j++)
                    kv[j] = *(const float4*)&Ks[(tx + 16 * j) * QPITCH + d];
#pragma unroll
                for (int i = 0; i < 4; i++)
#pragma unroll
                    for (int j = 0; j < 4; j++) {
                        s[i][j] += qv[i].x * kv[j].x;
                        s[i][j] += qv[i].y * kv[j].y;
                        s[i][j] += qv[i].z * kv[j].z;
                        s[i][j] += qv[i].w * kv[j].w;
                    }
            }
#pragma unroll
            for (int i = 0; i < 4; i++)
#pragma unroll
                for (int j = 0; j < 4; j++) {
                    int qg = q0 + ty + 8 * i;
                    int kg = k0 + tx + 16 * j;
                    float val = s[i][j] * SOFTMAX_SCALE;
                    Ss[(ty + 8 * i) * SPITCH + (tx + 16 * j)] =
                        (kg <= qg) ? val : -1e30f;
                }
            __syncthreads();

            // ---- phase B: online softmax update (4 threads per row) ----
            {
                int r = tid >> 2, seg = tid & 3;
                float* srow = Ss + r * SPITCH + seg * 16;
                float sv[16];
                float mloc = -1e30f;
#pragma unroll
                for (int c = 0; c < 16; c++) {
                    sv[c] = srow[c];
                    mloc  = fmaxf(mloc, sv[c]);
                }
                mloc = fmaxf(mloc, __shfl_xor_sync(0xffffffffu, mloc, 1));
                mloc = fmaxf(mloc, __shfl_xor_sync(0xffffffffu, mloc, 2));
                float mold = Ms[r];
                float mnew = fmaxf(mold, mloc);
                float lsum = 0.f;
#pragma unroll
                for (int c = 0; c < 16; c++) {
                    float pp = __expf(sv[c] - mnew);
                    srow[c]  = pp;
                    lsum    += pp;
                }
                lsum += __shfl_xor_sync(0xffffffffu, lsum, 1);
                lsum += __shfl_xor_sync(0xffffffffu, lsum, 2);
                if (seg == 0) {
                    float corr = __expf(mold - mnew);
                    Cs[r] = corr;
                    Ms[r] = mnew;
                    Ls[r] = Ls[r] * corr + lsum;
                }
            }
            __syncthreads();

            // ---- phase C: O = O*corr + P V ----
            float corr[4];
#pragma unroll
            for (int i = 0; i < 4; i++) corr[i] = Cs[ty + 8 * i];
#pragma unroll
            for (int i = 0; i < 4; i++)
#pragma unroll
                for (int j = 0; j < 8; j++) acc[i][j] *= corr[i];

#pragma unroll 4
            for (int kj = 0; kj < 64; kj++) {
                float4 v0 = *(const float4*)&Vs[kj * QPITCH + tx * 4];
                float4 v1 = *(const float4*)&Vs[kj * QPITCH + 64 + tx * 4];
#pragma unroll
                for (int i = 0; i < 4; i++) {
                    float pp = Ss[(ty + 8 * i) * SPITCH + kj];
                    acc[i][0] += pp * v0.x;
                    acc[i][1] += pp * v0.y;
                    acc[i][2] += pp * v0.z;
                    acc[i][3] += pp * v0.w;
                    acc[i][4] += pp * v1.x;
                    acc[i][5] += pp * v1.y;
                    acc[i][6] += pp * v1.z;
                    acc[i][7] += pp * v1.w;
                }
            }
        } // kt

        // epilogue: out[b][q0+row][:] = acc / l
        float* og = out + ((size_t)b * SEQ + q0) * HD;
#pragma unroll
        for (int i = 0; i < 4; i++) {
            float inv = 1.0f / Ls[ty + 8 * i];
            float4 o0 = make_float4(acc[i][0] * inv, acc[i][1] * inv,
                                    acc[i][2] * inv, acc[i][3] * inv);
            float4 o1 = make_float4(acc[i][4] * inv, acc[i][5] * inv,
                                    acc[i][6] * inv, acc[i][7] * inv);
            *(float4*)&og[(size_t)(ty + 8 * i) * HD + tx * 4]      = o0;
            *(float4*)&og[(size_t)(ty + 8 * i) * HD + 64 + tx * 4] = o1;
        }
    } // half
}

// ===========================================================================
// Launcher
// ===========================================================================
extern "C" void kernel_launch(void* const* d_in, const int* in_sizes, int n_in,
                              void* d_out, int out_size)
{
    // Identify inputs by size (robust to ordering):
    //   x: 4*2048*1024 = 8388608 ; mask: 2048*2048 (ignored, it is tril)
    //   Wq/Wk/Wv: 1024*128 = 131072 each (in declaration order)
    const float* x = nullptr;
    const float* W[3] = {nullptr, nullptr, nullptr};
    int wn = 0;
    for (int i = 0; i < n_in; i++) {
        if (in_sizes[i] == BATCH * SEQ * DIM) {
            x = (const float*)d_in[i];
        } else if (in_sizes[i] == DIM * HD && wn < 3) {
            W[wn++] = (const float*)d_in[i];
        }
    }
    float* out = (float*)d_out;

    cudaFuncSetAttribute(flash_attn_kernel,
                         cudaFuncAttributeMaxDynamicSharedMemorySize,
                         SMEM_ATTN_BYTES);

    qkv_gemm_kernel<<<dim3(BS / 128, 3), 256>>>(x, W[0], W[1], W[2]);
    flash_attn_kernel<<<dim3(32, BATCH), 128, SMEM_ATTN_BYTES>>>(out);
}

// round 3
// speedup vs baseline: 1.2315x; 1.2315x over previous
#include <cuda_runtime.h>
#include <cuda_bf16.h>
#include <cstdint>
#include <cstddef>

// ---------------------------------------------------------------------------
// GPT2Attention: B=4, S=2048, D=1024, HD=128, causal single-head.
// R3: projections via mma.sync bf16 (hi/lo 3-term split, fp32 accum) — the
//     plain-sm_100 ptxas target rejects tcgen05, HMMA via mma.sync works.
//     Flash attention fp32 SIMT at 256 threads.
// ---------------------------------------------------------------------------

#define BATCH 4
#define SEQ   2048
#define DIM   1024
#define HD    128
#define BS    (BATCH * SEQ)     // 8192 rows

__device__ float g_q[(size_t)BS * HD];
__device__ float g_k[(size_t)BS * HD];
__device__ float g_v[(size_t)BS * HD];
__device__ __align__(128) __nv_bfloat16 g_xh[(size_t)BS * DIM];
__device__ __align__(128) __nv_bfloat16 g_xl[(size_t)BS * DIM];
__device__ __align__(128) __nv_bfloat16 g_wth[3 * DIM * HD];   // [mat][n][k]
__device__ __align__(128) __nv_bfloat16 g_wtl[3 * DIM * HD];

// ============================ PTX helpers ==================================
__device__ __forceinline__ uint32_t smem_u32(const void* p) {
    uint32_t a;
    asm("{ .reg .u64 t; cvta.to.shared.u64 t, %1; cvt.u32.u64 %0, t; }"
        : "=r"(a) : "l"(p));
    return a;
}
#define CP_ASYNC16(dst, src) \
    asm volatile("cp.async.cg.shared.global [%0], [%1], 16;" :: "r"(dst), "l"(src))
#define CP_COMMIT()  asm volatile("cp.async.commit_group;" ::: "memory")
#define CP_WAIT1()   asm volatile("cp.async.wait_group 1;" ::: "memory")
#define CP_WAIT0()   asm volatile("cp.async.wait_group 0;" ::: "memory")

__device__ __forceinline__ void mma_bf16(float& d0, float& d1, float& d2, float& d3,
                                         uint32_t a0, uint32_t a1, uint32_t a2, uint32_t a3,
                                         uint32_t b0, uint32_t b1) {
    asm volatile(
        "mma.sync.aligned.m16n8k16.row.col.f32.bf16.bf16.f32 "
        "{%0,%1,%2,%3}, {%4,%5,%6,%7}, {%8,%9}, {%0,%1,%2,%3};"
        : "+f"(d0), "+f"(d1), "+f"(d2), "+f"(d3)
        : "r"(a0), "r"(a1), "r"(a2), "r"(a3), "r"(b0), "r"(b1));
}

// ===========================================================================
// Kernel 0a: x -> bf16 hi/lo split
// ===========================================================================
__global__ void convert_x_kernel(const float* __restrict__ x)
{
    for (size_t i = (size_t)blockIdx.x * blockDim.x + threadIdx.x;
         i < (size_t)BS * DIM; i += (size_t)gridDim.x * blockDim.x) {
        float v = x[i];
        __nv_bfloat16 h = __float2bfloat16(v);
        g_xh[i] = h;
        g_xl[i] = __float2bfloat16(v - __bfloat162float(h));
    }
}

// ===========================================================================
// Kernel 0b: W[k][n] -> W^T[n][k] bf16 hi/lo
// ===========================================================================
__global__ void convert_w_kernel(const float* __restrict__ Wq,
                                 const float* __restrict__ Wk,
                                 const float* __restrict__ Wv)
{
    const float* W = (blockIdx.y == 0) ? Wq : (blockIdx.y == 1) ? Wk : Wv;
    int idx = blockIdx.x * blockDim.x + threadIdx.x;   // n*1024 + k
    int n = idx >> 10, k = idx & 1023;
    float v = W[(size_t)k * HD + n];
    __nv_bfloat16 h = __float2bfloat16(v);
    size_t o = (size_t)blockIdx.y * DIM * HD + idx;
    g_wth[o] = h;
    g_wtl[o] = __float2bfloat16(v - __bfloat162float(h));
}

// ===========================================================================
// Kernel 1: mma.sync projection GEMM.
// Per CTA: M=64, N=128 (full), K=1024, BK=32, double-buffered cp.async.
// 8 warps as 2(M) x 4(N); warp tile 32x32 -> 2x4 m16n8k16 mma tiles.
// 3-term bf16 split: ah*bh + ah*bl + al*bh, fp32 accum.
// Smem pitch 80B/row (32 bf16 + 8 pad) -> conflict-free fragment LDS.
// grid = 384: mat = bid/128, m-tile = bid%128.
// ===========================================================================
#define PJ_BK       32
#define PJ_NC       (DIM / PJ_BK)        // 32 chunks
#define PJ_PITCH_B  80                   // bytes per smem row
#define PJ_PITCH_U  20                   // u32 per smem row
#define PJ_AH       0
#define PJ_AL       5120                 // 64*80
#define PJ_BH       10240
#define PJ_BL       20480                // + 128*80
#define PJ_STAGE_B  30720
#define PJ_SMEM     (2 * PJ_STAGE_B)     // 61440

__global__ void __launch_bounds__(256, 1)
qkv_mma_kernel()
{
    extern __shared__ __align__(16) char smem[];
    const uint32_t sb = smem_u32(smem);
    const int tid  = threadIdx.x;
    const int lane = tid & 31;
    const int warp = tid >> 5;
    const int wm   = warp >> 2;          // 0..1
    const int wn   = warp & 3;           // 0..3
    const int mat  = blockIdx.x >> 7;
    const int m0   = (blockIdx.x & 127) * 64;

    const __nv_bfloat16* xh  = g_xh;
    const __nv_bfloat16* xl  = g_xl;
    const __nv_bfloat16* wth = g_wth + (size_t)mat * DIM * HD;
    const __nv_bfloat16* wtl = g_wtl + (size_t)mat * DIM * HD;

    // ---- loader: 1536 x 16B chunks per stage, 6 per thread ----
    auto load_stage = [&](int chunk, int stage) {
        const int k0 = chunk * PJ_BK;
        const uint32_t st = sb + stage * PJ_STAGE_B;
#pragma unroll
        for (int t0 = 0; t0 < 6; t0++) {
            int t = tid + t0 * 256;
            const __nv_bfloat16* src;
            uint32_t dst;
            if (t < 512) {
                int rr = (t & 255) >> 2, c = t & 3;
                const __nv_bfloat16* base = (t < 256) ? xh : xl;
                src = base + (size_t)(m0 + rr) * DIM + k0 + c * 8;
                dst = st + ((t < 256) ? PJ_AH : PJ_AL) + rr * PJ_PITCH_B + c * 16;
            } else {
                int t2 = t - 512;
                int rr = (t2 & 511) >> 2, c = t2 & 3;
                const __nv_bfloat16* base = (t2 < 512) ? wth : wtl;
                src = base + (size_t)rr * DIM + k0 + c * 8;
                dst = st + ((t2 < 512) ? PJ_BH : PJ_BL) + rr * PJ_PITCH_B + c * 16;
            }
            CP_ASYNC16(dst, src);
        }
        CP_COMMIT();
    };

    float acc[2][4][4];
#pragma unroll
    for (int mt = 0; mt < 2; mt++)
#pragma unroll
        for (int nt = 0; nt < 4; nt++)
#pragma unroll
            for (int j = 0; j < 4; j++) acc[mt][nt][j] = 0.f;

    load_stage(0, 0);
    load_stage(1, 1);

    const int gr = lane >> 2;            // 0..7
    const int qo = lane & 3;             // u32 col within 8-elem group

    for (int i = 0; i < PJ_NC; i++) {
        if (i < PJ_NC - 1) CP_WAIT1(); else CP_WAIT0();
        __syncthreads();

        const uint32_t st = sb + (i & 1) * PJ_STAGE_B;
        const uint32_t* Ah = (const uint32_t*)(smem + (i & 1) * PJ_STAGE_B + PJ_AH);
        const uint32_t* Al = (const uint32_t*)(smem + (i & 1) * PJ_STAGE_B + PJ_AL);
        const uint32_t* Bh = (const uint32_t*)(smem + (i & 1) * PJ_STAGE_B + PJ_BH);
        const uint32_t* Bl = (const uint32_t*)(smem + (i & 1) * PJ_STAGE_B + PJ_BL);
        (void)st;

#pragma unroll
        for (int kk = 0; kk < 2; kk++) {
            const int ku = kk * 8 + qo;          // u32 index within row
            uint32_t ah[2][4], al[2][4], bh[4][2], bl[4][2];
#pragma unroll
            for (int mt = 0; mt < 2; mt++) {
                int r0 = (wm * 32 + mt * 16 + gr) * PJ_PITCH_U;
                int r8 = r0 + 8 * PJ_PITCH_U;
                ah[mt][0] = Ah[r0 + ku];      ah[mt][1] = Ah[r8 + ku];
                ah[mt][2] = Ah[r0 + ku + 4];  ah[mt][3] = Ah[r8 + ku + 4];
                al[mt][0] = Al[r0 + ku];      al[mt][1] = Al[r8 + ku];
                al[mt][2] = Al[r0 + ku + 4];  al[mt][3] = Al[r8 + ku + 4];
            }
#pragma unroll
            for (int nt = 0; nt < 4; nt++) {
                int rn = (wn * 32 + nt * 8 + gr) * PJ_PITCH_U;
                bh[nt][0] = Bh[rn + ku];  bh[nt][1] = Bh[rn + ku + 4];
                bl[nt][0] = Bl[rn + ku];  bl[nt][1] = Bl[rn + ku + 4];
            }
#pragma unroll
            for (int mt = 0; mt < 2; mt++)
#pragma unroll
                for (int nt = 0; nt < 4; nt++) {
                    float* d = acc[mt][nt];
                    mma_bf16(d[0], d[1], d[2], d[3],
                             ah[mt][0], ah[mt][1], ah[mt][2], ah[mt][3],
                             bh[nt][0], bh[nt][1]);
                    mma_bf16(d[0], d[1], d[2], d[3],
                             ah[mt][0], ah[mt][1], ah[mt][2], ah[mt][3],
                             bl[nt][0], bl[nt][1]);
                    mma_bf16(d[0], d[1], d[2], d[3],
                             al[mt][0], al[mt][1], al[mt][2], al[mt][3],
                             bh[nt][0], bh[nt][1]);
                }
        }
        __syncthreads();
        if (i + 2 < PJ_NC) load_stage(i + 2, (i & 1));
    }

    // ---- epilogue: accum layout c0,c1=(row,col),(row,col+1); c2,c3=row+8 ----
    float* outp = (mat == 0) ? g_q : (mat == 1) ? g_k : g_v;
#pragma unroll
    for (int mt = 0; mt < 2; mt++) {
        int row = m0 + wm * 32 + mt * 16 + gr;
#pragma unroll
        for (int nt = 0; nt < 4; nt++) {
            int col = wn * 32 + nt * 8 + 2 * qo;
            *(float2*)&outp[(size_t)row * HD + col] =
                make_float2(acc[mt][nt][0], acc[mt][nt][1]);
            *(float2*)&outp[(size_t)(row + 8) * HD + col] =
                make_float2(acc[mt][nt][2], acc[mt][nt][3]);
        }
    }
}

// ===========================================================================
// Kernel 2: causal flash attention, fp32 SIMT, 256 threads.
// BQ=32, BKT=64; block handles q-tile pair (p, 63-p). grid = (32, 4).
// ===========================================================================
#define QPITCH 132
#define SPITCH 68
#define SOFTMAX_SCALE 0.088388347648318447f   // 1/sqrt(128)
#define SM_Q   0
#define SM_K   (32 * QPITCH)
#define SM_V   (SM_K + 64 * QPITCH)
#define SM_S   (SM_V + 64 * QPITCH)
#define SM_M   (SM_S + 32 * SPITCH)
#define SM_L   (SM_M + 32)
#define SM_C   (SM_L + 32)
#define SMEM_ATTN_FLOATS (SM_C + 32)
#define SMEM_ATTN_BYTES  (SMEM_ATTN_FLOATS * 4)    // 93568 B

__global__ void __launch_bounds__(256, 1)
flash_attn_kernel(float* __restrict__ out)
{
    extern __shared__ __align__(16) float sm[];
    float* Qs = sm + SM_Q;
    float* Ks = sm + SM_K;
    float* Vs = sm + SM_V;
    float* Ss = sm + SM_S;
    float* Ms = sm + SM_M;
    float* Ls = sm + SM_L;
    float* Cs = sm + SM_C;

    const int b   = blockIdx.y;
    const int tid = threadIdx.x;
    const int ty  = tid >> 4;   // 0..15 -> rows {2ty, 2ty+1}
    const int tx  = tid & 15;

    const float* Qg = g_q + (size_t)b * SEQ * HD;
    const float* Kg = g_k + (size_t)b * SEQ * HD;
    const float* Vg = g_v + (size_t)b * SEQ * HD;

    for (int half = 0; half < 2; half++) {
        const int p  = half ? (63 - (int)blockIdx.x) : (int)blockIdx.x;
        const int q0 = p * 32;

        __syncthreads();

        for (int i = tid; i < 32 * 32; i += 256) {
            int r = i >> 5, c = (i & 31) * 4;
            *(float4*)&Qs[r * QPITCH + c] =
                *(const float4*)&Qg[(size_t)(q0 + r) * HD + c];
        }
        if (tid < 32) { Ms[tid] = -1e30f; Ls[tid] = 0.f; }

        float acc[2][8];
#pragma unroll
        for (int i = 0; i < 2; i++)
#pragma unroll
            for (int j = 0; j < 8; j++) acc[i][j] = 0.f;

        const int nkt = q0 / 64 + 1;
        for (int kt = 0; kt < nkt; kt++) {
            const int k0 = kt * 64;
            __syncthreads();
            for (int i = tid; i < 64 * 32; i += 256) {
                int r = i >> 5, c = (i & 31) * 4;
                *(float4*)&Ks[r * QPITCH + c] =
                    *(const float4*)&Kg[(size_t)(k0 + r) * HD + c];
                *(float4*)&Vs[r * QPITCH + c] =
                    *(const float4*)&Vg[(size_t)(k0 + r) * HD + c];
            }
            __syncthreads();

            // ---- phase A: S = Q K^T (scaled, causal-masked) ----
            float s[2][4];
#pragma unroll
            for (int i = 0; i < 2; i++)
#pragma unroll
                for (int j = 0; j < 4; j++) s[i][j] = 0.f;

#pragma unroll 8
            for (int d = 0; d < HD; d += 4) {
                float4 qv[2], kv[4];
#pragma unroll
                for (int i = 0; i < 2; i++)
                    qv[i] = *(const float4*)&Qs[(2 * ty + i) * QPITCH + d];
#pragma unroll
                for (int j = 0; j < 4; j++)
                    kv[j] = *(const float4*)&Ks[(tx + 16 * j) * QPITCH + d];
#pragma unroll
                for (int i = 0; i < 2; i++)
#pragma unroll
                    for (int j = 0; j < 4; j++) {
                        s[i][j] += qv[i].x * kv[j].x;
                        s[i][j] += qv[i].y * kv[j].y;
                        s[i][j] += qv[i].z * kv[j].z;
                        s[i][j] += qv[i].w * kv[j].w;
                    }
            }
#pragma unroll
            for (int i = 0; i < 2; i++)
#pragma unroll
                for (int j = 0; j < 4; j++) {
                    int qg = q0 + 2 * ty + i;
                    int kg = k0 + tx + 16 * j;
                    float val = s[i][j] * SOFTMAX_SCALE;
                    Ss[(2 * ty + i) * SPITCH + (tx + 16 * j)] =
                        (kg <= qg) ? val : -1e30f;
                }
            __syncthreads();

            // ---- phase B: online softmax (8 threads/row, 8 cols each) ----
            {
                int r = tid >> 3, seg = tid & 7;
                float* srow = Ss + r * SPITCH + seg * 8;
                float sv[8];
                float mloc = -1e30f;
#pragma unroll
                for (int c = 0; c < 8; c++) {
                    sv[c] = srow[c];
                    mloc  = fmaxf(mloc, sv[c]);
                }
                mloc = fmaxf(mloc, __shfl_xor_sync(0xffffffffu, mloc, 1));
                mloc = fmaxf(mloc, __shfl_xor_sync(0xffffffffu, mloc, 2));
                mloc = fmaxf(mloc, __shfl_xor_sync(0xffffffffu, mloc, 4));
                float mold = Ms[r];
                float mnew = fmaxf(mold, mloc);
                float lsum = 0.f;
#pragma unroll
                for (int c = 0; c < 8; c++) {
                    float pp = __expf(sv[c] - mnew);
                    srow[c]  = pp;
                    lsum    += pp;
                }
                lsum += __shfl_xor_sync(0xffffffffu, lsum, 1);
                lsum += __shfl_xor_sync(0xffffffffu, lsum, 2);
                lsum += __shfl_xor_sync(0xffffffffu, lsum, 4);
                if (seg == 0) {
                    float corr = __expf(mold - mnew);
                    Cs[r] = corr;
                    Ms[r] = mnew;
                    Ls[r] = Ls[r] * corr + lsum;
                }
            }
            __syncthreads();

            // ---- phase C: O = O*corr + P V ----
            float corr[2];
#pragma unroll
            for (int i = 0; i < 2; i++) corr[i] = Cs[2 * ty + i];
#pragma unroll
            for (int i = 0; i < 2; i++)
#pragma unroll
                for (int j = 0; j < 8; j++) acc[i][j] *= corr[i];

#pragma unroll 4
            for (int kj = 0; kj < 64; kj++) {
                float4 v0 = *(const float4*)&Vs[kj * QPITCH + tx * 4];
                float4 v1 = *(const float4*)&Vs[kj * QPITCH + 64 + tx * 4];
#pragma unroll
                for (int i = 0; i < 2; i++) {
                    float pp = Ss[(2 * ty + i) * SPITCH + kj];
                    acc[i][0] += pp * v0.x;
                    acc[i][1] += pp * v0.y;
                    acc[i][2] += pp * v0.z;
                    acc[i][3] += pp * v0.w;
                    acc[i][4] += pp * v1.x;
                    acc[i][5] += pp * v1.y;
                    acc[i][6] += pp * v1.z;
                    acc[i][7] += pp * v1.w;
                }
            }
        } // kt

        float* og = out + ((size_t)b * SEQ + q0) * HD;
#pragma unroll
        for (int i = 0; i < 2; i++) {
            float inv = 1.0f / Ls[2 * ty + i];
            float4 o0 = make_float4(acc[i][0] * inv, acc[i][1] * inv,
                                    acc[i][2] * inv, acc[i][3] * inv);
            float4 o1 = make_float4(acc[i][4] * inv, acc[i][5] * inv,
                                    acc[i][6] * inv, acc[i][7] * inv);
            *(float4*)&og[(size_t)(2 * ty + i) * HD + tx * 4]      = o0;
            *(float4*)&og[(size_t)(2 * ty + i) * HD + 64 + tx * 4] = o1;
        }
    } // half
}

// ===========================================================================
// Launcher
// ===========================================================================
extern "C" void kernel_launch(void* const* d_in, const int* in_sizes, int n_in,
                              void* d_out, int out_size)
{
    const float* x = nullptr;
    const float* W[3] = {nullptr, nullptr, nullptr};
    int wn = 0;
    for (int i = 0; i < n_in; i++) {
        if (in_sizes[i] == BATCH * SEQ * DIM) {
            x = (const float*)d_in[i];
        } else if (in_sizes[i] == DIM * HD && wn < 3) {
            W[wn++] = (const float*)d_in[i];
        }
    }
    float* out = (float*)d_out;

    cudaFuncSetAttribute(qkv_mma_kernel,
                         cudaFuncAttributeMaxDynamicSharedMemorySize, PJ_SMEM);
    cudaFuncSetAttribute(flash_attn_kernel,
                         cudaFuncAttributeMaxDynamicSharedMemorySize, SMEM_ATTN_BYTES);

    convert_x_kernel<<<2048, 256>>>(x);
    convert_w_kernel<<<dim3(512, 3), 256>>>(W[0], W[1], W[2]);
    qkv_mma_kernel<<<384, 256, PJ_SMEM>>>();
    flash_attn_kernel<<<dim3(32, BATCH), 256, SMEM_ATTN_BYTES>>>(out);
}

// round 4
// speedup vs baseline: 2.0512x; 1.6657x over previous
#include <cuda_runtime.h>
#include <cuda_bf16.h>
#include <cstdint>
#include <cstddef>

// ---------------------------------------------------------------------------
// GPT2Attention: B=4, S=2048, D=1024, HD=128, causal single-head.
// R4: projections AND flash attention on mma.sync bf16 (hi/lo 3-term split,
//     fp32 accum). Projection writes Q/K bf16 hi/lo and V TRANSPOSED hi/lo
//     so flash attention needs no conversion and V is mma-B-operand ready.
// ---------------------------------------------------------------------------

#define BATCH 4
#define SEQ   2048
#define DIM   1024
#define HD    128
#define BS    (BATCH * SEQ)     // 8192 rows
#define SOFTMAX_SCALE 0.088388347648318447f   // 1/sqrt(128)

// Scratch (device globals: allocation-free per harness rules)
__device__ __align__(128) __nv_bfloat16 g_xh[(size_t)BS * DIM];
__device__ __align__(128) __nv_bfloat16 g_xl[(size_t)BS * DIM];
__device__ __align__(128) __nv_bfloat16 g_wth[3 * DIM * HD];   // [mat][n][k]
__device__ __align__(128) __nv_bfloat16 g_wtl[3 * DIM * HD];
__device__ __align__(128) __nv_bfloat16 g_qh[(size_t)BS * HD];
__device__ __align__(128) __nv_bfloat16 g_ql[(size_t)BS * HD];
__device__ __align__(128) __nv_bfloat16 g_kh[(size_t)BS * HD];
__device__ __align__(128) __nv_bfloat16 g_kl[(size_t)BS * HD];
__device__ __align__(128) __nv_bfloat16 g_vth[(size_t)BS * HD]; // [b][hd][s]
__device__ __align__(128) __nv_bfloat16 g_vtl[(size_t)BS * HD];

// ============================ PTX helpers ==================================
__device__ __forceinline__ uint32_t smem_u32(const void* p) {
    uint32_t a;
    asm("{ .reg .u64 t; cvta.to.shared.u64 t, %1; cvt.u32.u64 %0, t; }"
        : "=r"(a) : "l"(p));
    return a;
}
#define CP_ASYNC16(dst, src) \
    asm volatile("cp.async.cg.shared.global [%0], [%1], 16;" :: "r"(dst), "l"(src))
#define CP_COMMIT()  asm volatile("cp.async.commit_group;" ::: "memory")
#define CP_WAIT1()   asm volatile("cp.async.wait_group 1;" ::: "memory")
#define CP_WAIT0()   asm volatile("cp.async.wait_group 0;" ::: "memory")

__device__ __forceinline__ void mma_bf16(float& d0, float& d1, float& d2, float& d3,
                                         uint32_t a0, uint32_t a1, uint32_t a2, uint32_t a3,
                                         uint32_t b0, uint32_t b1) {
    asm volatile(
        "mma.sync.aligned.m16n8k16.row.col.f32.bf16.bf16.f32 "
        "{%0,%1,%2,%3}, {%4,%5,%6,%7}, {%8,%9}, {%0,%1,%2,%3};"
        : "+f"(d0), "+f"(d1), "+f"(d2), "+f"(d3)
        : "r"(a0), "r"(a1), "r"(a2), "r"(a3), "r"(b0), "r"(b1));
}

// pack two floats -> bf16x2 hi + bf16x2 residual
__device__ __forceinline__ void split_pack(float x, float y,
                                           uint32_t& hi, uint32_t& lo) {
    __nv_bfloat162 h2 = __floats2bfloat162_rn(x, y);
    hi = *(uint32_t*)&h2;
    __nv_bfloat162 l2 = __floats2bfloat162_rn(x - __low2float(h2),
                                              y - __high2float(h2));
    lo = *(uint32_t*)&l2;
}

// ===========================================================================
// Kernel 0a: x -> bf16 hi/lo split
// ===========================================================================
__global__ void convert_x_kernel(const float* __restrict__ x)
{
    for (size_t i = (size_t)blockIdx.x * blockDim.x + threadIdx.x;
         i < (size_t)BS * DIM; i += (size_t)gridDim.x * blockDim.x) {
        float v = x[i];
        __nv_bfloat16 h = __float2bfloat16(v);
        g_xh[i] = h;
        g_xl[i] = __float2bfloat16(v - __bfloat162float(h));
    }
}

// ===========================================================================
// Kernel 0b: W[k][n] -> W^T[n][k] bf16 hi/lo
// ===========================================================================
__global__ void convert_w_kernel(const float* __restrict__ Wq,
                                 const float* __restrict__ Wk,
                                 const float* __restrict__ Wv)
{
    const float* W = (blockIdx.y == 0) ? Wq : (blockIdx.y == 1) ? Wk : Wv;
    int idx = blockIdx.x * blockDim.x + threadIdx.x;   // n*1024 + k
    int n = idx >> 10, k = idx & 1023;
    float v = W[(size_t)k * HD + n];
    __nv_bfloat16 h = __float2bfloat16(v);
    size_t o = (size_t)blockIdx.y * DIM * HD + idx;
    g_wth[o] = h;
    g_wtl[o] = __float2bfloat16(v - __bfloat162float(h));
}

// ===========================================================================
// Kernel 1: mma.sync projection GEMM.
// Per CTA: M=64, N=128, K=1024, BK=32, double-buffered cp.async.
// 8 warps 2(M) x 4(N); warp tile 32x32. 3-term split.
// Epilogue: mat 0/1 -> bf16 hi/lo row-major; mat 2 -> V^T hi/lo [b][hd][s].
// grid = 384.
// ===========================================================================
#define PJ_BK       32
#define PJ_NC       (DIM / PJ_BK)        // 32 chunks
#define PJ_PITCH_B  80
#define PJ_PITCH_U  20
#define PJ_AH       0
#define PJ_AL       5120
#define PJ_BH       10240
#define PJ_BL       20480
#define PJ_STAGE_B  30720
#define PJ_SMEM     (2 * PJ_STAGE_B)     // 61440

__global__ void __launch_bounds__(256, 1)
qkv_mma_kernel()
{
    extern __shared__ __align__(16) char smem[];
    const uint32_t sb = smem_u32(smem);
    const int tid  = threadIdx.x;
    const int lane = tid & 31;
    const int warp = tid >> 5;
    const int wm   = warp >> 2;
    const int wn   = warp & 3;
    const int mat  = blockIdx.x >> 7;
    const int m0   = (blockIdx.x & 127) * 64;

    const __nv_bfloat16* xh  = g_xh;
    const __nv_bfloat16* xl  = g_xl;
    const __nv_bfloat16* wth = g_wth + (size_t)mat * DIM * HD;
    const __nv_bfloat16* wtl = g_wtl + (size_t)mat * DIM * HD;

    auto load_stage = [&](int chunk, int stage) {
        const int k0 = chunk * PJ_BK;
        const uint32_t st = sb + stage * PJ_STAGE_B;
#pragma unroll
        for (int t0 = 0; t0 < 6; t0++) {
            int t = tid + t0 * 256;
            const __nv_bfloat16* src;
            uint32_t dst;
            if (t < 512) {
                int rr = (t & 255) >> 2, c = t & 3;
                const __nv_bfloat16* base = (t < 256) ? xh : xl;
                src = base + (size_t)(m0 + rr) * DIM + k0 + c * 8;
                dst = st + ((t < 256) ? PJ_AH : PJ_AL) + rr * PJ_PITCH_B + c * 16;
            } else {
                int t2 = t - 512;
                int rr = (t2 & 511) >> 2, c = t2 & 3;
                const __nv_bfloat16* base = (t2 < 512) ? wth : wtl;
                src = base + (size_t)rr * DIM + k0 + c * 8;
                dst = st + ((t2 < 512) ? PJ_BH : PJ_BL) + rr * PJ_PITCH_B + c * 16;
            }
            CP_ASYNC16(dst, src);
        }
        CP_COMMIT();
    };

    float acc[2][4][4];
#pragma unroll
    for (int mt = 0; mt < 2; mt++)
#pragma unroll
        for (int nt = 0; nt < 4; nt++)
#pragma unroll
            for (int j = 0; j < 4; j++) acc[mt][nt][j] = 0.f;

    load_stage(0, 0);
    load_stage(1, 1);

    const int gr = lane >> 2;
    const int qo = lane & 3;

    for (int i = 0; i < PJ_NC; i++) {
        if (i < PJ_NC - 1) CP_WAIT1(); else CP_WAIT0();
        __syncthreads();

        const uint32_t* Ah = (const uint32_t*)(smem + (i & 1) * PJ_STAGE_B + PJ_AH);
        const uint32_t* Al = (const uint32_t*)(smem + (i & 1) * PJ_STAGE_B + PJ_AL);
        const uint32_t* Bh = (const uint32_t*)(smem + (i & 1) * PJ_STAGE_B + PJ_BH);
        const uint32_t* Bl = (const uint32_t*)(smem + (i & 1) * PJ_STAGE_B + PJ_BL);

#pragma unroll
        for (int kk = 0; kk < 2; kk++) {
            const int ku = kk * 8 + qo;
            uint32_t ah[2][4], al[2][4], bh[4][2], bl[4][2];
#pragma unroll
            for (int mt = 0; mt < 2; mt++) {
                int r0 = (wm * 32 + mt * 16 + gr) * PJ_PITCH_U;
                int r8 = r0 + 8 * PJ_PITCH_U;
                ah[mt][0] = Ah[r0 + ku];      ah[mt][1] = Ah[r8 + ku];
                ah[mt][2] = Ah[r0 + ku + 4];  ah[mt][3] = Ah[r8 + ku + 4];
                al[mt][0] = Al[r0 + ku];      al[mt][1] = Al[r8 + ku];
                al[mt][2] = Al[r0 + ku + 4];  al[mt][3] = Al[r8 + ku + 4];
            }
#pragma unroll
            for (int nt = 0; nt < 4; nt++) {
                int rn = (wn * 32 + nt * 8 + gr) * PJ_PITCH_U;
                bh[nt][0] = Bh[rn + ku];  bh[nt][1] = Bh[rn + ku + 4];
                bl[nt][0] = Bl[rn + ku];  bl[nt][1] = Bl[rn + ku + 4];
            }
#pragma unroll
            for (int mt = 0; mt < 2; mt++)
#pragma unroll
                for (int nt = 0; nt < 4; nt++) {
                    float* d = acc[mt][nt];
                    mma_bf16(d[0], d[1], d[2], d[3],
                             ah[mt][0], ah[mt][1], ah[mt][2], ah[mt][3],
                             bh[nt][0], bh[nt][1]);
                    mma_bf16(d[0], d[1], d[2], d[3],
                             ah[mt][0], ah[mt][1], ah[mt][2], ah[mt][3],
                             bl[nt][0], bl[nt][1]);
                    mma_bf16(d[0], d[1], d[2], d[3],
                             al[mt][0], al[mt][1], al[mt][2], al[mt][3],
                             bh[nt][0], bh[nt][1]);
                }
        }
        __syncthreads();
        if (i + 2 < PJ_NC) load_stage(i + 2, (i & 1));
    }

    // ---- epilogue ----
    if (mat < 2) {
        __nv_bfloat16* oh = (mat == 0) ? g_qh : g_kh;
        __nv_bfloat16* ol = (mat == 0) ? g_ql : g_kl;
#pragma unroll
        for (int mt = 0; mt < 2; mt++) {
            int row = m0 + wm * 32 + mt * 16 + gr;
#pragma unroll
            for (int nt = 0; nt < 4; nt++) {
                int col = wn * 32 + nt * 8 + 2 * qo;
                uint32_t h01, l01, h23, l23;
                split_pack(acc[mt][nt][0], acc[mt][nt][1], h01, l01);
                split_pack(acc[mt][nt][2], acc[mt][nt][3], h23, l23);
                *(uint32_t*)&oh[(size_t)row * HD + col]       = h01;
                *(uint32_t*)&ol[(size_t)row * HD + col]       = l01;
                *(uint32_t*)&oh[(size_t)(row + 8) * HD + col] = h23;
                *(uint32_t*)&ol[(size_t)(row + 8) * HD + col] = l23;
            }
        }
    } else {
        // V transposed: vt[b][col][s]
        const int bb = m0 >> 11;
        const int s0 = m0 & 2047;
#pragma unroll
        for (int mt = 0; mt < 2; mt++) {
            int srow = s0 + wm * 32 + mt * 16 + gr;
#pragma unroll
            for (int nt = 0; nt < 4; nt++) {
                int col = wn * 32 + nt * 8 + 2 * qo;
                size_t base = ((size_t)bb * HD + col) * SEQ;
#pragma unroll
                for (int j = 0; j < 4; j++) {
                    float v = acc[mt][nt][j];
                    size_t idx = base + ((j & 1) ? SEQ : 0) + srow + ((j >> 1) * 8);
                    __nv_bfloat16 h = __float2bfloat16(v);
                    g_vth[idx] = h;
                    g_vtl[idx] = __float2bfloat16(v - __bfloat162float(h));
                }
            }
        }
    }
}

// ===========================================================================
// Kernel 2: tensor-core causal flash attention (FA-2 warp-over-M).
// BQ=64 (4 warps x 16 rows), BK=64, HD=128, 128 threads.
// Full hi/lo split for QK^T and PV (3-term each), fp32 softmax.
// grid = (32, 4): blockIdx.x = q-tile p (q0 = 64p, nkt = p+1), y = batch.
// Smem: Qh,Ql (pitch 272B) + 2 stages of {Kh,Kl (272B), Vth,Vtl (144B)}.
// ===========================================================================
#define FA_SQH   0
#define FA_SQL   17408
#define FA_STG   34816
#define FA_KH    0
#define FA_KL    17408
#define FA_VTH   34816
#define FA_VTL   53248
#define FA_STGSZ 71680
#define FA_SMEM  (FA_STG + 2 * FA_STGSZ)     // 178176

__global__ void __launch_bounds__(128, 1)
flash_tc_kernel(float* __restrict__ out)
{
    extern __shared__ __align__(16) char smem[];
    const uint32_t sb = smem_u32(smem);
    const int tid  = threadIdx.x;
    const int lane = tid & 31;
    const int warp = tid >> 5;
    const int gr   = lane >> 2;
    const int qo   = lane & 3;
    const int p    = blockIdx.x;
    const int b    = blockIdx.y;
    const int q0   = p * 64;
    const int nkt  = p + 1;

    auto load_stage = [&](int kt, int stage) {
        const int k0 = kt * 64;
        const uint32_t st = sb + FA_STG + stage * FA_STGSZ;
        const size_t krow0 = (size_t)(b * SEQ + k0) * HD;
        const size_t vrow0 = (size_t)b * HD * SEQ + k0;
#pragma unroll
        for (int t0 = 0; t0 < 32; t0++) {
            int t = tid + t0 * 128;
            int region = t >> 10, sub = t & 1023;
            const __nv_bfloat16* src;
            uint32_t dst;
            if (region < 2) {
                int r = sub >> 4, c = sub & 15;
                src = ((region == 0) ? g_kh : g_kl) + krow0 + (size_t)r * HD + c * 8;
                dst = st + ((region == 0) ? FA_KH : FA_KL) + r * 272 + c * 16;
            } else {
                int r = sub >> 3, c = sub & 7;
                src = ((region == 2) ? g_vth : g_vtl) + vrow0 + (size_t)r * SEQ + c * 8;
                dst = st + ((region == 2) ? FA_VTH : FA_VTL) + r * 144 + c * 16;
            }
            CP_ASYNC16(dst, src);
        }
        CP_COMMIT();
    };

    // prologue: async K/V stages first, then Q (plain loads overlap them)
    load_stage(0, 0);
    if (nkt > 1) load_stage(1, 1);
    for (int t = tid; t < 2048; t += 128) {
        int m = t >> 10, r = (t >> 4) & 63, c = t & 15;
        const __nv_bfloat16* src =
            ((m == 0) ? g_qh : g_ql) + (size_t)(b * SEQ + q0 + r) * HD + c * 8;
        float4 v = *(const float4*)src;
        *(float4*)(smem + ((m == 0) ? FA_SQH : FA_SQL) + r * 272 + c * 16) = v;
    }

    float o[16][4];
#pragma unroll
    for (int nt = 0; nt < 16; nt++)
#pragma unroll
        for (int j = 0; j < 4; j++) o[nt][j] = 0.f;
    float mr0 = -1e30f, mr1 = -1e30f, l0 = 0.f, l1 = 0.f;

    const int r0 = (16 * warp + gr) * 68;
    const int r8 = r0 + 8 * 68;
    const uint32_t* QH = (const uint32_t*)(smem + FA_SQH);
    const uint32_t* QL = (const uint32_t*)(smem + FA_SQL);

    for (int kt = 0; kt < nkt; kt++) {
        if (kt + 1 < nkt) CP_WAIT1(); else CP_WAIT0();
        __syncthreads();

        const char* st = smem + FA_STG + (kt & 1) * FA_STGSZ;
        const uint32_t* KH = (const uint32_t*)(st + FA_KH);
        const uint32_t* KL = (const uint32_t*)(st + FA_KL);
        const uint32_t* VH = (const uint32_t*)(st + FA_VTH);
        const uint32_t* VL = (const uint32_t*)(st + FA_VTL);

        // ---- S = Q K^T (3-term split) ----
        float s[8][4];
#pragma unroll
        for (int nt = 0; nt < 8; nt++)
#pragma unroll
            for (int j = 0; j < 4; j++) s[nt][j] = 0.f;

#pragma unroll
        for (int kk = 0; kk < 8; kk++) {
            const int ku = kk * 8 + qo;
            uint32_t ah0 = QH[r0 + ku], ah1 = QH[r8 + ku];
            uint32_t ah2 = QH[r0 + ku + 4], ah3 = QH[r8 + ku + 4];
            uint32_t al0 = QL[r0 + ku], al1 = QL[r8 + ku];
            uint32_t al2 = QL[r0 + ku + 4], al3 = QL[r8 + ku + 4];
#pragma unroll
            for (int nt = 0; nt < 8; nt++) {
                int rn = (8 * nt + gr) * 68;
                uint32_t bh0 = KH[rn + ku], bh1 = KH[rn + ku + 4];
                uint32_t bl0 = KL[rn + ku], bl1 = KL[rn + ku + 4];
                mma_bf16(s[nt][0], s[nt][1], s[nt][2], s[nt][3],
                         ah0, ah1, ah2, ah3, bh0, bh1);
                mma_bf16(s[nt][0], s[nt][1], s[nt][2], s[nt][3],
                         ah0, ah1, ah2, ah3, bl0, bl1);
                mma_bf16(s[nt][0], s[nt][1], s[nt][2], s[nt][3],
                         al0, al1, al2, al3, bh0, bh1);
            }
        }

        // ---- scale + causal mask (only diagonal tile is partial) ----
#pragma unroll
        for (int nt = 0; nt < 8; nt++)
#pragma unroll
            for (int j = 0; j < 4; j++) s[nt][j] *= SOFTMAX_SCALE;

        if (kt == nkt - 1) {
            const int qr0 = q0 + 16 * warp + gr;
            const int qr1 = qr0 + 8;
            const int k0v = kt * 64;
#pragma unroll
            for (int nt = 0; nt < 8; nt++) {
                int c0 = k0v + 8 * nt + 2 * qo, c1 = c0 + 1;
                if (c0 > qr0) s[nt][0] = -1e30f;
                if (c1 > qr0) s[nt][1] = -1e30f;
                if (c0 > qr1) s[nt][2] = -1e30f;
                if (c1 > qr1) s[nt][3] = -1e30f;
            }
        }

        // ---- online softmax (warp-local, rows gr / gr+8) ----
        float mx0 = -1e30f, mx1 = -1e30f;
#pragma unroll
        for (int nt = 0; nt < 8; nt++) {
            mx0 = fmaxf(mx0, fmaxf(s[nt][0], s[nt][1]));
            mx1 = fmaxf(mx1, fmaxf(s[nt][2], s[nt][3]));
        }
        mx0 = fmaxf(mx0, __shfl_xor_sync(0xffffffffu, mx0, 1));
        mx0 = fmaxf(mx0, __shfl_xor_sync(0xffffffffu, mx0, 2));
        mx1 = fmaxf(mx1, __shfl_xor_sync(0xffffffffu, mx1, 1));
        mx1 = fmaxf(mx1, __shfl_xor_sync(0xffffffffu, mx1, 2));
        float mn0 = fmaxf(mr0, mx0), mn1 = fmaxf(mr1, mx1);
        float corr0 = __expf(mr0 - mn0), corr1 = __expf(mr1 - mn1);
        mr0 = mn0; mr1 = mn1;

        float ls0 = 0.f, ls1 = 0.f;
#pragma unroll
        for (int nt = 0; nt < 8; nt++) {
            s[nt][0] = __expf(s[nt][0] - mn0); ls0 += s[nt][0];
            s[nt][1] = __expf(s[nt][1] - mn0); ls0 += s[nt][1];
            s[nt][2] = __expf(s[nt][2] - mn1); ls1 += s[nt][2];
            s[nt][3] = __expf(s[nt][3] - mn1); ls1 += s[nt][3];
        }
        ls0 += __shfl_xor_sync(0xffffffffu, ls0, 1);
        ls0 += __shfl_xor_sync(0xffffffffu, ls0, 2);
        ls1 += __shfl_xor_sync(0xffffffffu, ls1, 1);
        ls1 += __shfl_xor_sync(0xffffffffu, ls1, 2);
        l0 = l0 * corr0 + ls0;
        l1 = l1 * corr1 + ls1;

#pragma unroll
        for (int nt = 0; nt < 16; nt++) {
            o[nt][0] *= corr0; o[nt][1] *= corr0;
            o[nt][2] *= corr1; o[nt][3] *= corr1;
        }

        // ---- O += P V (P hi/lo from S fragments; V^T as B operand) ----
#pragma unroll
        for (int kp = 0; kp < 4; kp++) {
            const int t0 = 2 * kp, t1 = 2 * kp + 1;
            uint32_t ah0, al0, ah1, al1, ah2, al2, ah3, al3;
            split_pack(s[t0][0], s[t0][1], ah0, al0);
            split_pack(s[t0][2], s[t0][3], ah1, al1);
            split_pack(s[t1][0], s[t1][1], ah2, al2);
            split_pack(s[t1][2], s[t1][3], ah3, al3);
            const int ku = 8 * kp + qo;
#pragma unroll
            for (int nt = 0; nt < 16; nt++) {
                int rn = (8 * nt + gr) * 36;
                uint32_t bh0 = VH[rn + ku], bh1 = VH[rn + ku + 4];
                uint32_t bl0 = VL[rn + ku], bl1 = VL[rn + ku + 4];
                mma_bf16(o[nt][0], o[nt][1], o[nt][2], o[nt][3],
                         ah0, ah1, ah2, ah3, bh0, bh1);
                mma_bf16(o[nt][0], o[nt][1], o[nt][2], o[nt][3],
                         ah0, ah1, ah2, ah3, bl0, bl1);
                mma_bf16(o[nt][0], o[nt][1], o[nt][2], o[nt][3],
                         al0, al1, al2, al3, bh0, bh1);
            }
        }

        __syncthreads();
        if (kt + 2 < nkt) load_stage(kt + 2, kt & 1);
    }

    // ---- epilogue ----
    const float inv0 = 1.0f / l0;
    const float inv1 = 1.0f / l1;
    float* og  = out + ((size_t)b * SEQ + q0 + 16 * warp + gr) * HD;
    float* og8 = og + 8 * HD;
#pragma unroll
    for (int nt = 0; nt < 16; nt++) {
        int c = 8 * nt + 2 * qo;
        *(float2*)&og[c]  = make_float2(o[nt][0] * inv0, o[nt][1] * inv0);
        *(float2*)&og8[c] = make_float2(o[nt][2] * inv1, o[nt][3] * inv1);
    }
}

// ===========================================================================
// Launcher
// ===========================================================================
extern "C" void kernel_launch(void* const* d_in, const int* in_sizes, int n_in,
                              void* d_out, int out_size)
{
    const float* x = nullptr;
    const float* W[3] = {nullptr, nullptr, nullptr};
    int wn = 0;
    for (int i = 0; i < n_in; i++) {
        if (in_sizes[i] == BATCH * SEQ * DIM) {
            x = (const float*)d_in[i];
        } else if (in_sizes[i] == DIM * HD && wn < 3) {
            W[wn++] = (const float*)d_in[i];
        }
    }
    float* out = (float*)d_out;

    cudaFuncSetAttribute(qkv_mma_kernel,
                         cudaFuncAttributeMaxDynamicSharedMemorySize, PJ_SMEM);
    cudaFuncSetAttribute(flash_tc_kernel,
                         cudaFuncAttributeMaxDynamicSharedMemorySize, FA_SMEM);

    convert_x_kernel<<<2048, 256>>>(x);
    convert_w_kernel<<<dim3(512, 3), 256>>>(W[0], W[1], W[2]);
    qkv_mma_kernel<<<384, 256, PJ_SMEM>>>();
    flash_tc_kernel<<<dim3(32, BATCH), 128, FA_SMEM>>>(out);
}

// round 5
// speedup vs baseline: 2.3105x; 1.1264x over previous
#include <cuda_runtime.h>
#include <cuda_bf16.h>
#include <cstdint>
#include <cstddef>

// ---------------------------------------------------------------------------
// GPT2Attention: B=4, S=2048, D=1024, HD=128, causal single-head.
// R5: (1) MMA issue reordering (term-outer -> independent accumulator chains)
//     in both GEMM and flash; (2) flash rebuilt as 148 perfectly-balanced
//     persistent blocks over a flat (q-tile, kv-chunk) range with split-KV
//     partials + combine kernel.
// ---------------------------------------------------------------------------

#define BATCH 4
#define SEQ   2048
#define DIM   1024
#define HD    128
#define BS    (BATCH * SEQ)     // 8192 rows
#define SOFTMAX_SCALE 0.088388347648318447f   // 1/sqrt(128)

// flash schedule: per batch 32 q-tiles (BQ=64), tile p has p+1 kv-chunks (BK=64)
#define FA_TILES   32
#define FA_FLAT    528          // sum p+1 = 32*33/2
#define FA_BLKS_PB 37           // blocks per batch
#define FA_BLKS    (FA_BLKS_PB * BATCH)   // 148 = one wave
#define FA_MAXSLOT 4

// Scratch (device globals: allocation-free per harness rules)
__device__ __align__(128) __nv_bfloat16 g_xh[(size_t)BS * DIM];
__device__ __align__(128) __nv_bfloat16 g_xl[(size_t)BS * DIM];
__device__ __align__(128) __nv_bfloat16 g_wth[3 * DIM * HD];   // [mat][n][k]
__device__ __align__(128) __nv_bfloat16 g_wtl[3 * DIM * HD];
__device__ __align__(128) __nv_bfloat16 g_qh[(size_t)BS * HD];
__device__ __align__(128) __nv_bfloat16 g_ql[(size_t)BS * HD];
__device__ __align__(128) __nv_bfloat16 g_kh[(size_t)BS * HD];
__device__ __align__(128) __nv_bfloat16 g_kl[(size_t)BS * HD];
__device__ __align__(128) __nv_bfloat16 g_vth[(size_t)BS * HD]; // [b][hd][s]
__device__ __align__(128) __nv_bfloat16 g_vtl[(size_t)BS * HD];
// split-KV partials: [b][tile][slot] -> o 64x128, m/l 64
__device__ __align__(128) float g_po[(size_t)BATCH * FA_TILES * FA_MAXSLOT * 64 * 128];
__device__ float g_pm[BATCH * FA_TILES * FA_MAXSLOT * 64];
__device__ float g_pl[BATCH * FA_TILES * FA_MAXSLOT * 64];

// ============================ PTX helpers ==================================
__device__ __forceinline__ uint32_t smem_u32(const void* p) {
    uint32_t a;
    asm("{ .reg .u64 t; cvta.to.shared.u64 t, %1; cvt.u32.u64 %0, t; }"
        : "=r"(a) : "l"(p));
    return a;
}
#define CP_ASYNC16(dst, src) \
    asm volatile("cp.async.cg.shared.global [%0], [%1], 16;" :: "r"(dst), "l"(src))
#define CP_COMMIT()  asm volatile("cp.async.commit_group;" ::: "memory")
#define CP_WAIT1()   asm volatile("cp.async.wait_group 1;" ::: "memory")
#define CP_WAIT0()   asm volatile("cp.async.wait_group 0;" ::: "memory")

__device__ __forceinline__ void mma_bf16(float& d0, float& d1, float& d2, float& d3,
                                         uint32_t a0, uint32_t a1, uint32_t a2, uint32_t a3,
                                         uint32_t b0, uint32_t b1) {
    asm volatile(
        "mma.sync.aligned.m16n8k16.row.col.f32.bf16.bf16.f32 "
        "{%0,%1,%2,%3}, {%4,%5,%6,%7}, {%8,%9}, {%0,%1,%2,%3};"
        : "+f"(d0), "+f"(d1), "+f"(d2), "+f"(d3)
        : "r"(a0), "r"(a1), "r"(a2), "r"(a3), "r"(b0), "r"(b1));
}

__device__ __forceinline__ void split_pack(float x, float y,
                                           uint32_t& hi, uint32_t& lo) {
    __nv_bfloat162 h2 = __floats2bfloat162_rn(x, y);
    hi = *(uint32_t*)&h2;
    __nv_bfloat162 l2 = __floats2bfloat162_rn(x - __low2float(h2),
                                              y - __high2float(h2));
    lo = *(uint32_t*)&l2;
}

// flat-range schedule: S(j) = start flat index of block j (per batch)
__device__ __forceinline__ int fa_S(int j) { return (j * FA_FLAT) / FA_BLKS_PB; }
__device__ __forceinline__ int fa_block_of(int f) {
    int j = (f * FA_BLKS_PB) / FA_FLAT;
    while (fa_S(j + 1) <= f) j++;
    while (fa_S(j) > f) j--;
    return j;
}

// ===========================================================================
// Kernel 0a: x -> bf16 hi/lo split
// ===========================================================================
__global__ void convert_x_kernel(const float* __restrict__ x)
{
    for (size_t i = (size_t)blockIdx.x * blockDim.x + threadIdx.x;
         i < (size_t)BS * DIM; i += (size_t)gridDim.x * blockDim.x) {
        float v = x[i];
        __nv_bfloat16 h = __float2bfloat16(v);
        g_xh[i] = h;
        g_xl[i] = __float2bfloat16(v - __bfloat162float(h));
    }
}

// ===========================================================================
// Kernel 0b: W[k][n] -> W^T[n][k] bf16 hi/lo
// ===========================================================================
__global__ void convert_w_kernel(const float* __restrict__ Wq,
                                 const float* __restrict__ Wk,
                                 const float* __restrict__ Wv)
{
    const float* W = (blockIdx.y == 0) ? Wq : (blockIdx.y == 1) ? Wk : Wv;
    int idx = blockIdx.x * blockDim.x + threadIdx.x;   // n*1024 + k
    int n = idx >> 10, k = idx & 1023;
    float v = W[(size_t)k * HD + n];
    __nv_bfloat16 h = __float2bfloat16(v);
    size_t o = (size_t)blockIdx.y * DIM * HD + idx;
    g_wth[o] = h;
    g_wtl[o] = __float2bfloat16(v - __bfloat162float(h));
}

// ===========================================================================
// Kernel 1: mma.sync projection GEMM (term-outer MMA ordering).
// Per CTA: M=64, N=128, K=1024, BK=32, double-buffered cp.async. grid = 384.
// ===========================================================================
#define PJ_BK       32
#define PJ_NC       (DIM / PJ_BK)
#define PJ_PITCH_B  80
#define PJ_PITCH_U  20
#define PJ_AH       0
#define PJ_AL       5120
#define PJ_BH       10240
#define PJ_BL       20480
#define PJ_STAGE_B  30720
#define PJ_SMEM     (2 * PJ_STAGE_B)     // 61440

__global__ void __launch_bounds__(256, 1)
qkv_mma_kernel()
{
    extern __shared__ __align__(16) char smem[];
    const uint32_t sb = smem_u32(smem);
    const int tid  = threadIdx.x;
    const int lane = tid & 31;
    const int warp = tid >> 5;
    const int wm   = warp >> 2;
    const int wn   = warp & 3;
    const int mat  = blockIdx.x >> 7;
    const int m0   = (blockIdx.x & 127) * 64;

    const __nv_bfloat16* xh  = g_xh;
    const __nv_bfloat16* xl  = g_xl;
    const __nv_bfloat16* wth = g_wth + (size_t)mat * DIM * HD;
    const __nv_bfloat16* wtl = g_wtl + (size_t)mat * DIM * HD;

    auto load_stage = [&](int chunk, int stage) {
        const int k0 = chunk * PJ_BK;
        const uint32_t st = sb + stage * PJ_STAGE_B;
#pragma unroll
        for (int t0 = 0; t0 < 6; t0++) {
            int t = tid + t0 * 256;
            const __nv_bfloat16* src;
            uint32_t dst;
            if (t < 512) {
                int rr = (t & 255) >> 2, c = t & 3;
                const __nv_bfloat16* base = (t < 256) ? xh : xl;
                src = base + (size_t)(m0 + rr) * DIM + k0 + c * 8;
                dst = st + ((t < 256) ? PJ_AH : PJ_AL) + rr * PJ_PITCH_B + c * 16;
            } else {
                int t2 = t - 512;
                int rr = (t2 & 511) >> 2, c = t2 & 3;
                const __nv_bfloat16* base = (t2 < 512) ? wth : wtl;
                src = base + (size_t)rr * DIM + k0 + c * 8;
                dst = st + ((t2 < 512) ? PJ_BH : PJ_BL) + rr * PJ_PITCH_B + c * 16;
            }
            CP_ASYNC16(dst, src);
        }
        CP_COMMIT();
    };

    float acc[2][4][4];
#pragma unroll
    for (int mt = 0; mt < 2; mt++)
#pragma unroll
        for (int nt = 0; nt < 4; nt++)
#pragma unroll
            for (int j = 0; j < 4; j++) acc[mt][nt][j] = 0.f;

    load_stage(0, 0);
    load_stage(1, 1);

    const int gr = lane >> 2;
    const int qo = lane & 3;

    for (int i = 0; i < PJ_NC; i++) {
        if (i < PJ_NC - 1) CP_WAIT1(); else CP_WAIT0();
        __syncthreads();

        const uint32_t* Ah = (const uint32_t*)(smem + (i & 1) * PJ_STAGE_B + PJ_AH);
        const uint32_t* Al = (const uint32_t*)(smem + (i & 1) * PJ_STAGE_B + PJ_AL);
        const uint32_t* Bh = (const uint32_t*)(smem + (i & 1) * PJ_STAGE_B + PJ_BH);
        const uint32_t* Bl = (const uint32_t*)(smem + (i & 1) * PJ_STAGE_B + PJ_BL);

#pragma unroll
        for (int kk = 0; kk < 2; kk++) {
            const int ku = kk * 8 + qo;
            uint32_t ah[2][4], al[2][4], bh[4][2], bl[4][2];
#pragma unroll
            for (int mt = 0; mt < 2; mt++) {
                int r0 = (wm * 32 + mt * 16 + gr) * PJ_PITCH_U;
                int r8 = r0 + 8 * PJ_PITCH_U;
                ah[mt][0] = Ah[r0 + ku];      ah[mt][1] = Ah[r8 + ku];
                ah[mt][2] = Ah[r0 + ku + 4];  ah[mt][3] = Ah[r8 + ku + 4];
                al[mt][0] = Al[r0 + ku];      al[mt][1] = Al[r8 + ku];
                al[mt][2] = Al[r0 + ku + 4];  al[mt][3] = Al[r8 + ku + 4];
            }
#pragma unroll
            for (int nt = 0; nt < 4; nt++) {
                int rn = (wn * 32 + nt * 8 + gr) * PJ_PITCH_U;
                bh[nt][0] = Bh[rn + ku];  bh[nt][1] = Bh[rn + ku + 4];
                bl[nt][0] = Bl[rn + ku];  bl[nt][1] = Bl[rn + ku + 4];
            }
            // term-outer: 8 independent MMAs per term
#pragma unroll
            for (int mt = 0; mt < 2; mt++)
#pragma unroll
                for (int nt = 0; nt < 4; nt++)
                    mma_bf16(acc[mt][nt][0], acc[mt][nt][1], acc[mt][nt][2], acc[mt][nt][3],
                             ah[mt][0], ah[mt][1], ah[mt][2], ah[mt][3],
                             bh[nt][0], bh[nt][1]);
#pragma unroll
            for (int mt = 0; mt < 2; mt++)
#pragma unroll
                for (int nt = 0; nt < 4; nt++)
                    mma_bf16(acc[mt][nt][0], acc[mt][nt][1], acc[mt][nt][2], acc[mt][nt][3],
                             ah[mt][0], ah[mt][1], ah[mt][2], ah[mt][3],
                             bl[nt][0], bl[nt][1]);
#pragma unroll
            for (int mt = 0; mt < 2; mt++)
#pragma unroll
                for (int nt = 0; nt < 4; nt++)
                    mma_bf16(acc[mt][nt][0], acc[mt][nt][1], acc[mt][nt][2], acc[mt][nt][3],
                             al[mt][0], al[mt][1], al[mt][2], al[mt][3],
                             bh[nt][0], bh[nt][1]);
        }
        __syncthreads();
        if (i + 2 < PJ_NC) load_stage(i + 2, (i & 1));
    }

    // ---- epilogue ----
    if (mat < 2) {
        __nv_bfloat16* oh = (mat == 0) ? g_qh : g_kh;
        __nv_bfloat16* ol = (mat == 0) ? g_ql : g_kl;
#pragma unroll
        for (int mt = 0; mt < 2; mt++) {
            int row = m0 + wm * 32 + mt * 16 + gr;
#pragma unroll
            for (int nt = 0; nt < 4; nt++) {
                int col = wn * 32 + nt * 8 + 2 * qo;
                uint32_t h01, l01, h23, l23;
                split_pack(acc[mt][nt][0], acc[mt][nt][1], h01, l01);
                split_pack(acc[mt][nt][2], acc[mt][nt][3], h23, l23);
                *(uint32_t*)&oh[(size_t)row * HD + col]       = h01;
                *(uint32_t*)&ol[(size_t)row * HD + col]       = l01;
                *(uint32_t*)&oh[(size_t)(row + 8) * HD + col] = h23;
                *(uint32_t*)&ol[(size_t)(row + 8) * HD + col] = l23;
            }
        }
    } else {
        const int bb = m0 >> 11;
        const int s0 = m0 & 2047;
#pragma unroll
        for (int mt = 0; mt < 2; mt++) {
            int srow = s0 + wm * 32 + mt * 16 + gr;
#pragma unroll
            for (int nt = 0; nt < 4; nt++) {
                int col = wn * 32 + nt * 8 + 2 * qo;
                size_t base = ((size_t)bb * HD + col) * SEQ;
#pragma unroll
                for (int j = 0; j < 4; j++) {
                    float v = acc[mt][nt][j];
                    size_t idx = base + ((j & 1) ? SEQ : 0) + srow + ((j >> 1) * 8);
                    __nv_bfloat16 h = __float2bfloat16(v);
                    g_vth[idx] = h;
                    g_vtl[idx] = __float2bfloat16(v - __bfloat162float(h));
                }
            }
        }
    }
}

// ===========================================================================
// Kernel 2: balanced tensor-core causal flash attention.
// 148 blocks; block (b, j) processes per-batch flat iters [S(j), S(j+1)),
// spanning one or more q-tiles. Whole tiles -> direct output; partial tiles
// -> (o, m, l) slot merged by fa_combine_kernel.
// BQ=64 (4 warps x 16 rows), BK=64, 128 threads, grouped term-outer MMAs.
// ===========================================================================
#define FA_SQH   0
#define FA_SQL   17408
#define FA_STG   34816
#define FA_KH    0
#define FA_KL    17408
#define FA_VTH   34816
#define FA_VTL   53248
#define FA_STGSZ 71680
#define FA_SMEM  (FA_STG + 2 * FA_STGSZ)     // 178176

__global__ void __launch_bounds__(128, 1)
flash_tc_kernel(float* __restrict__ out)
{
    extern __shared__ __align__(16) char smem[];
    const uint32_t sb = smem_u32(smem);
    const int tid  = threadIdx.x;
    const int lane = tid & 31;
    const int warp = tid >> 5;
    const int gr   = lane >> 2;
    const int qo   = lane & 3;
    const int b    = blockIdx.x / FA_BLKS_PB;
    const int j    = blockIdx.x % FA_BLKS_PB;
    const int s_f  = fa_S(j);
    const int e_f  = fa_S(j + 1);

    auto load_stage = [&](int c, int stage) {
        const int k0 = c * 64;
        const uint32_t st = sb + FA_STG + stage * FA_STGSZ;
        const size_t krow0 = (size_t)(b * SEQ + k0) * HD;
        const size_t vrow0 = (size_t)b * HD * SEQ + k0;
#pragma unroll
        for (int t0 = 0; t0 < 32; t0++) {
            int t = tid + t0 * 128;
            int region = t >> 10, sub = t & 1023;
            const __nv_bfloat16* src;
            uint32_t dst;
            if (region < 2) {
                int r = sub >> 4, cc = sub & 15;
                src = ((region == 0) ? g_kh : g_kl) + krow0 + (size_t)r * HD + cc * 8;
                dst = st + ((region == 0) ? FA_KH : FA_KL) + r * 272 + cc * 16;
            } else {
                int r = sub >> 3, cc = sub & 7;
                src = ((region == 2) ? g_vth : g_vtl) + vrow0 + (size_t)r * SEQ + cc * 8;
                dst = st + ((region == 2) ? FA_VTH : FA_VTL) + r * 144 + cc * 16;
            }
            CP_ASYNC16(dst, src);
        }
        CP_COMMIT();
    };

    const int r0 = (16 * warp + gr) * 68;
    const int r8 = r0 + 8 * 68;
    const uint32_t* QH = (const uint32_t*)(smem + FA_SQH);
    const uint32_t* QL = (const uint32_t*)(smem + FA_SQL);

    int f = s_f;
    while (f < e_f) {
        // decode q-tile: p(p+1)/2 <= f < (p+1)(p+2)/2
        int p = (int)((sqrtf(8.f * (float)f + 1.f) - 1.f) * 0.5f);
        while ((p + 1) * (p + 2) / 2 <= f) p++;
        while (p * (p + 1) / 2 > f) p--;
        const int f0     = p * (p + 1) / 2;
        const int cstart = f - f0;
        const int cend   = min(p + 1, e_f - f0);
        const int q0     = p * 64;

        __syncthreads();   // protect smem reuse across tiles

        // prefetch kv stages, then Q tile via plain loads
        load_stage(cstart, 0);
        if (cstart + 1 < cend) load_stage(cstart + 1, 1);
        for (int t = tid; t < 2048; t += 128) {
            int m = t >> 10, r = (t >> 4) & 63, c = t & 15;
            const __nv_bfloat16* src =
                ((m == 0) ? g_qh : g_ql) + (size_t)(b * SEQ + q0 + r) * HD + c * 8;
            float4 v = *(const float4*)src;
            *(float4*)(smem + ((m == 0) ? FA_SQH : FA_SQL) + r * 272 + c * 16) = v;
        }

        float o[16][4];
#pragma unroll
        for (int nt = 0; nt < 16; nt++)
#pragma unroll
            for (int jj = 0; jj < 4; jj++) o[nt][jj] = 0.f;
        float mr0 = -1e30f, mr1 = -1e30f, l0 = 0.f, l1 = 0.f;

        for (int c = cstart; c < cend; c++) {
            if (c + 1 < cend) CP_WAIT1(); else CP_WAIT0();
            __syncthreads();

            const char* st = smem + FA_STG + ((c - cstart) & 1) * FA_STGSZ;
            const uint32_t* KH = (const uint32_t*)(st + FA_KH);
            const uint32_t* KL = (const uint32_t*)(st + FA_KL);
            const uint32_t* VH = (const uint32_t*)(st + FA_VTH);
            const uint32_t* VL = (const uint32_t*)(st + FA_VTL);

            // ---- S = Q K^T (grouped term-outer: 4 indep per term) ----
            float s[8][4];
#pragma unroll
            for (int nt = 0; nt < 8; nt++)
#pragma unroll
                for (int jj = 0; jj < 4; jj++) s[nt][jj] = 0.f;

#pragma unroll
            for (int kk = 0; kk < 8; kk++) {
                const int ku = kk * 8 + qo;
                uint32_t ah0 = QH[r0 + ku], ah1 = QH[r8 + ku];
                uint32_t ah2 = QH[r0 + ku + 4], ah3 = QH[r8 + ku + 4];
                uint32_t al0 = QL[r0 + ku], al1 = QL[r8 + ku];
                uint32_t al2 = QL[r0 + ku + 4], al3 = QL[r8 + ku + 4];
#pragma unroll
                for (int g = 0; g < 2; g++) {
                    uint32_t bh[4][2], bl[4][2];
#pragma unroll
                    for (int t = 0; t < 4; t++) {
                        int rn = (8 * (4 * g + t) + gr) * 68;
                        bh[t][0] = KH[rn + ku];  bh[t][1] = KH[rn + ku + 4];
                        bl[t][0] = KL[rn + ku];  bl[t][1] = KL[rn + ku + 4];
                    }
#pragma unroll
                    for (int t = 0; t < 4; t++) {
                        int nt = 4 * g + t;
                        mma_bf16(s[nt][0], s[nt][1], s[nt][2], s[nt][3],
                                 ah0, ah1, ah2, ah3, bh[t][0], bh[t][1]);
                    }
#pragma unroll
                    for (int t = 0; t < 4; t++) {
                        int nt = 4 * g + t;
                        mma_bf16(s[nt][0], s[nt][1], s[nt][2], s[nt][3],
                                 ah0, ah1, ah2, ah3, bl[t][0], bl[t][1]);
                    }
#pragma unroll
                    for (int t = 0; t < 4; t++) {
                        int nt = 4 * g + t;
                        mma_bf16(s[nt][0], s[nt][1], s[nt][2], s[nt][3],
                                 al0, al1, al2, al3, bh[t][0], bh[t][1]);
                    }
                }
            }

#pragma unroll
            for (int nt = 0; nt < 8; nt++)
#pragma unroll
                for (int jj = 0; jj < 4; jj++) s[nt][jj] *= SOFTMAX_SCALE;

            if (c == p) {   // diagonal chunk: causal mask
                const int qr0 = q0 + 16 * warp + gr;
                const int qr1 = qr0 + 8;
                const int k0v = c * 64;
#pragma unroll
                for (int nt = 0; nt < 8; nt++) {
                    int c0 = k0v + 8 * nt + 2 * qo, c1 = c0 + 1;
                    if (c0 > qr0) s[nt][0] = -1e30f;
                    if (c1 > qr0) s[nt][1] = -1e30f;
                    if (c0 > qr1) s[nt][2] = -1e30f;
                    if (c1 > qr1) s[nt][3] = -1e30f;
                }
            }

            // ---- online softmax (warp-local) ----
            float mx0 = -1e30f, mx1 = -1e30f;
#pragma unroll
            for (int nt = 0; nt < 8; nt++) {
                mx0 = fmaxf(mx0, fmaxf(s[nt][0], s[nt][1]));
                mx1 = fmaxf(mx1, fmaxf(s[nt][2], s[nt][3]));
            }
            mx0 = fmaxf(mx0, __shfl_xor_sync(0xffffffffu, mx0, 1));
            mx0 = fmaxf(mx0, __shfl_xor_sync(0xffffffffu, mx0, 2));
            mx1 = fmaxf(mx1, __shfl_xor_sync(0xffffffffu, mx1, 1));
            mx1 = fmaxf(mx1, __shfl_xor_sync(0xffffffffu, mx1, 2));
            float mn0 = fmaxf(mr0, mx0), mn1 = fmaxf(mr1, mx1);
            float corr0 = __expf(mr0 - mn0), corr1 = __expf(mr1 - mn1);
            mr0 = mn0; mr1 = mn1;

            float ls0 = 0.f, ls1 = 0.f;
#pragma unroll
            for (int nt = 0; nt < 8; nt++) {
                s[nt][0] = __expf(s[nt][0] - mn0); ls0 += s[nt][0];
                s[nt][1] = __expf(s[nt][1] - mn0); ls0 += s[nt][1];
                s[nt][2] = __expf(s[nt][2] - mn1); ls1 += s[nt][2];
                s[nt][3] = __expf(s[nt][3] - mn1); ls1 += s[nt][3];
            }
            ls0 += __shfl_xor_sync(0xffffffffu, ls0, 1);
            ls0 += __shfl_xor_sync(0xffffffffu, ls0, 2);
            ls1 += __shfl_xor_sync(0xffffffffu, ls1, 1);
            ls1 += __shfl_xor_sync(0xffffffffu, ls1, 2);
            l0 = l0 * corr0 + ls0;
            l1 = l1 * corr1 + ls1;

#pragma unroll
            for (int nt = 0; nt < 16; nt++) {
                o[nt][0] *= corr0; o[nt][1] *= corr0;
                o[nt][2] *= corr1; o[nt][3] *= corr1;
            }

            // ---- O += P V (grouped term-outer) ----
#pragma unroll
            for (int kp = 0; kp < 4; kp++) {
                const int t0 = 2 * kp, t1 = 2 * kp + 1;
                uint32_t ah0, al0, ah1, al1, ah2, al2, ah3, al3;
                split_pack(s[t0][0], s[t0][1], ah0, al0);
                split_pack(s[t0][2], s[t0][3], ah1, al1);
                split_pack(s[t1][0], s[t1][1], ah2, al2);
                split_pack(s[t1][2], s[t1][3], ah3, al3);
                const int ku = 8 * kp + qo;
#pragma unroll
                for (int g = 0; g < 4; g++) {
                    uint32_t vh[4][2], vl[4][2];
#pragma unroll
                    for (int t = 0; t < 4; t++) {
                        int rn = (8 * (4 * g + t) + gr) * 36;
                        vh[t][0] = VH[rn + ku];  vh[t][1] = VH[rn + ku + 4];
                        vl[t][0] = VL[rn + ku];  vl[t][1] = VL[rn + ku + 4];
                    }
#pragma unroll
                    for (int t = 0; t < 4; t++) {
                        int nt = 4 * g + t;
                        mma_bf16(o[nt][0], o[nt][1], o[nt][2], o[nt][3],
                                 ah0, ah1, ah2, ah3, vh[t][0], vh[t][1]);
                    }
#pragma unroll
                    for (int t = 0; t < 4; t++) {
                        int nt = 4 * g + t;
                        mma_bf16(o[nt][0], o[nt][1], o[nt][2], o[nt][3],
                                 ah0, ah1, ah2, ah3, vl[t][0], vl[t][1]);
                    }
#pragma unroll
                    for (int t = 0; t < 4; t++) {
                        int nt = 4 * g + t;
                        mma_bf16(o[nt][0], o[nt][1], o[nt][2], o[nt][3],
                                 al0, al1, al2, al3, vh[t][0], vh[t][1]);
                    }
                }
            }

            __syncthreads();
            if (c + 2 < cend) load_stage(c + 2, (c - cstart) & 1);
        } // chunks

        // ---- tile epilogue ----
        const int row0 = 16 * warp + gr;
        if (cstart == 0 && cend == p + 1) {
            // whole tile: normalize and write final
            const float inv0 = 1.0f / l0;
            const float inv1 = 1.0f / l1;
            float* og  = out + ((size_t)b * SEQ + q0 + row0) * HD;
            float* og8 = og + 8 * HD;
#pragma unroll
            for (int nt = 0; nt < 16; nt++) {
                int cc = 8 * nt + 2 * qo;
                *(float2*)&og[cc]  = make_float2(o[nt][0] * inv0, o[nt][1] * inv0);
                *(float2*)&og8[cc] = make_float2(o[nt][2] * inv1, o[nt][3] * inv1);
            }
        } else {
            // partial: write (o, m, l) into slot (j - first block of tile)
            const int slot = j - fa_block_of(f0);
            const size_t base = ((size_t)(b * FA_TILES + p)) * FA_MAXSLOT + slot;
            if (qo == 0) {
                g_pm[base * 64 + row0]     = mr0;
                g_pl[base * 64 + row0]     = l0;
                g_pm[base * 64 + row0 + 8] = mr1;
                g_pl[base * 64 + row0 + 8] = l1;
            }
            float* po  = g_po + (base * 64 + row0) * 128;
            float* po8 = po + 8 * 128;
#pragma unroll
            for (int nt = 0; nt < 16; nt++) {
                int cc = 8 * nt + 2 * qo;
                *(float2*)&po[cc]  = make_float2(o[nt][0], o[nt][1]);
                *(float2*)&po8[cc] = make_float2(o[nt][2], o[nt][3]);
            }
        }

        f = f0 + cend;
    } // tiles
}

// ===========================================================================
// Kernel 3: combine split-KV partials. grid = BATCH*FA_TILES, 64 threads.
// ===========================================================================
__global__ void fa_combine_kernel(float* __restrict__ out)
{
    const int p = blockIdx.x & (FA_TILES - 1);
    const int b = blockIdx.x >> 5;
    const int f0 = p * (p + 1) / 2;
    const int j0 = fa_block_of(f0);
    const int j1 = fa_block_of(f0 + p);
    if (j0 == j1) return;                    // single block wrote final
    const int ns = j1 - j0 + 1;
    const int r  = threadIdx.x;              // 0..63

    const size_t base = ((size_t)(b * FA_TILES + p)) * FA_MAXSLOT;
    float m = -1e30f;
    for (int i = 0; i < ns; i++) m = fmaxf(m, g_pm[(base + i) * 64 + r]);
    float w[FA_MAXSLOT];
    float l = 0.f;
    for (int i = 0; i < ns; i++) {
        w[i] = __expf(g_pm[(base + i) * 64 + r] - m);
        l += g_pl[(base + i) * 64 + r] * w[i];
    }
    const float inv = 1.0f / l;

    float* og = out + ((size_t)b * SEQ + p * 64 + r) * HD;
    for (int c = 0; c < HD; c += 4) {
        float4 acc = make_float4(0.f, 0.f, 0.f, 0.f);
        for (int i = 0; i < ns; i++) {
            const float4 v = *(const float4*)&g_po[((base + i) * 64 + r) * 128 + c];
            acc.x += v.x * w[i]; acc.y += v.y * w[i];
            acc.z += v.z * w[i]; acc.w += v.w * w[i];
        }
        *(float4*)&og[c] = make_float4(acc.x * inv, acc.y * inv,
                                       acc.z * inv, acc.w * inv);
    }
}

// ===========================================================================
// Launcher
// ===========================================================================
extern "C" void kernel_launch(void* const* d_in, const int* in_sizes, int n_in,
                              void* d_out, int out_size)
{
    const float* x = nullptr;
    const float* W[3] = {nullptr, nullptr, nullptr};
    int wn = 0;
    for (int i = 0; i < n_in; i++) {
        if (in_sizes[i] == BATCH * SEQ * DIM) {
            x = (const float*)d_in[i];
        } else if (in_sizes[i] == DIM * HD && wn < 3) {
            W[wn++] = (const float*)d_in[i];
        }
    }
    float* out = (float*)d_out;

    cudaFuncSetAttribute(qkv_mma_kernel,
                         cudaFuncAttributeMaxDynamicSharedMemorySize, PJ_SMEM);
    cudaFuncSetAttribute(flash_tc_kernel,
                         cudaFuncAttributeMaxDynamicSharedMemorySize, FA_SMEM);

    convert_x_kernel<<<2048, 256>>>(x);
    convert_w_kernel<<<dim3(512, 3), 256>>>(W[0], W[1], W[2]);
    qkv_mma_kernel<<<384, 256, PJ_SMEM>>>();
    flash_tc_kernel<<<FA_BLKS, 128, FA_SMEM>>>(out);
    fa_combine_kernel<<<BATCH * FA_TILES, 64>>>(out);
}

// round 6
// speedup vs baseline: 2.4731x; 1.0704x over previous
#include <cuda_runtime.h>
#include <cuda_bf16.h>
#include <cstdint>
#include <cstddef>

// ---------------------------------------------------------------------------
// GPT2Attention: B=4, S=2048, D=1024, HD=128, causal single-head.
// R6: flash widened to 8 warps (BQ=128); qkv BK=64 + 2 CTAs/SM;
//     vectorized convert. All tensor math mma.sync bf16 hi/lo 3-term.
// ---------------------------------------------------------------------------

#define BATCH 4
#define SEQ   2048
#define DIM   1024
#define HD    128
#define BS    (BATCH * SEQ)
#define SOFTMAX_SCALE 0.088388347648318447f   // 1/sqrt(128)

// flash schedule: per batch 16 q-tiles (BQ=128), tile p has 2p+2 kv-chunks (BK=64)
#define FA_TILES   16
#define FA_FLAT    272          // sum (2p+2), p=0..15
#define FA_BLKS_PB 37
#define FA_BLKS    (FA_BLKS_PB * BATCH)   // 148
#define FA_MAXSLOT 8

// Scratch (device globals: allocation-free per harness rules)
__device__ __align__(128) __nv_bfloat16 g_xh[(size_t)BS * DIM];
__device__ __align__(128) __nv_bfloat16 g_xl[(size_t)BS * DIM];
__device__ __align__(128) __nv_bfloat16 g_wth[3 * DIM * HD];   // [mat][n][k]
__device__ __align__(128) __nv_bfloat16 g_wtl[3 * DIM * HD];
__device__ __align__(128) __nv_bfloat16 g_qh[(size_t)BS * HD];
__device__ __align__(128) __nv_bfloat16 g_ql[(size_t)BS * HD];
__device__ __align__(128) __nv_bfloat16 g_kh[(size_t)BS * HD];
__device__ __align__(128) __nv_bfloat16 g_kl[(size_t)BS * HD];
__device__ __align__(128) __nv_bfloat16 g_vth[(size_t)BS * HD]; // [b][hd][s]
__device__ __align__(128) __nv_bfloat16 g_vtl[(size_t)BS * HD];
// split-KV partials: [b][tile][slot] -> o 128x128, m/l 128
__device__ __align__(128) float g_po[(size_t)BATCH * FA_TILES * FA_MAXSLOT * 128 * 128];
__device__ float g_pm[BATCH * FA_TILES * FA_MAXSLOT * 128];
__device__ float g_pl[BATCH * FA_TILES * FA_MAXSLOT * 128];

// ============================ PTX helpers ==================================
__device__ __forceinline__ uint32_t smem_u32(const void* p) {
    uint32_t a;
    asm("{ .reg .u64 t; cvta.to.shared.u64 t, %1; cvt.u32.u64 %0, t; }"
        : "=r"(a) : "l"(p));
    return a;
}
#define CP_ASYNC16(dst, src) \
    asm volatile("cp.async.cg.shared.global [%0], [%1], 16;" :: "r"(dst), "l"(src))
#define CP_COMMIT()  asm volatile("cp.async.commit_group;" ::: "memory")
#define CP_WAIT1()   asm volatile("cp.async.wait_group 1;" ::: "memory")
#define CP_WAIT0()   asm volatile("cp.async.wait_group 0;" ::: "memory")

__device__ __forceinline__ void mma_bf16(float& d0, float& d1, float& d2, float& d3,
                                         uint32_t a0, uint32_t a1, uint32_t a2, uint32_t a3,
                                         uint32_t b0, uint32_t b1) {
    asm volatile(
        "mma.sync.aligned.m16n8k16.row.col.f32.bf16.bf16.f32 "
        "{%0,%1,%2,%3}, {%4,%5,%6,%7}, {%8,%9}, {%0,%1,%2,%3};"
        : "+f"(d0), "+f"(d1), "+f"(d2), "+f"(d3)
        : "r"(a0), "r"(a1), "r"(a2), "r"(a3), "r"(b0), "r"(b1));
}

__device__ __forceinline__ void split_pack(float x, float y,
                                           uint32_t& hi, uint32_t& lo) {
    __nv_bfloat162 h2 = __floats2bfloat162_rn(x, y);
    hi = *(uint32_t*)&h2;
    __nv_bfloat162 l2 = __floats2bfloat162_rn(x - __low2float(h2),
                                              y - __high2float(h2));
    lo = *(uint32_t*)&l2;
}

// flat-range schedule helpers
__device__ __forceinline__ int fa_S(int j) { return (j * FA_FLAT) / FA_BLKS_PB; }
__device__ __forceinline__ int fa_block_of(int f) {
    int j = (f * FA_BLKS_PB) / FA_FLAT;
    while (fa_S(j + 1) <= f) j++;
    while (fa_S(j) > f) j--;
    return j;
}

// ===========================================================================
// Kernel 0a: x -> bf16 hi/lo split (vectorized float4)
// ===========================================================================
__global__ void convert_x_kernel(const float* __restrict__ x)
{
    for (size_t i = (size_t)blockIdx.x * blockDim.x + threadIdx.x;
         i < (size_t)BS * DIM / 4; i += (size_t)gridDim.x * blockDim.x) {
        float4 v = *(const float4*)&x[i * 4];
        uint32_t h0, l0, h1, l1;
        split_pack(v.x, v.y, h0, l0);
        split_pack(v.z, v.w, h1, l1);
        *(uint2*)&g_xh[i * 4] = make_uint2(h0, h1);
        *(uint2*)&g_xl[i * 4] = make_uint2(l0, l1);
    }
}

// ===========================================================================
// Kernel 0b: W[k][n] -> W^T[n][k] bf16 hi/lo
// ===========================================================================
__global__ void convert_w_kernel(const float* __restrict__ Wq,
                                 const float* __restrict__ Wk,
                                 const float* __restrict__ Wv)
{
    const float* W = (blockIdx.y == 0) ? Wq : (blockIdx.y == 1) ? Wk : Wv;
    int idx = blockIdx.x * blockDim.x + threadIdx.x;   // n*1024 + k
    int n = idx >> 10, k = idx & 1023;
    float v = W[(size_t)k * HD + n];
    __nv_bfloat16 h = __float2bfloat16(v);
    size_t o = (size_t)blockIdx.y * DIM * HD + idx;
    g_wth[o] = h;
    g_wtl[o] = __float2bfloat16(v - __bfloat162float(h));
}

// ===========================================================================
// Kernel 1: mma.sync projection GEMM. BM=64, N=128, BK=64 (16 chunks),
// double-buffered cp.async, 2 CTAs/SM target. grid = 384.
// ===========================================================================
#define PJ_BK       64
#define PJ_NC       (DIM / PJ_BK)        // 16
#define PJ_PITCH_B  144                  // 64 bf16 = 128B + 16 pad
#define PJ_PITCH_U  36
#define PJ_AH       0
#define PJ_AL       9216                 // 64*144
#define PJ_BH       18432
#define PJ_BL       36864                // 18432 + 128*144
#define PJ_STAGE_B  55296
#define PJ_SMEM     (2 * PJ_STAGE_B)     // 110592

__global__ void __launch_bounds__(256, 2)
qkv_mma_kernel()
{
    extern __shared__ __align__(16) char smem[];
    const uint32_t sb = smem_u32(smem);
    const int tid  = threadIdx.x;
    const int lane = tid & 31;
    const int warp = tid >> 5;
    const int wm   = warp >> 2;
    const int wn   = warp & 3;
    const int mat  = blockIdx.x >> 7;
    const int m0   = (blockIdx.x & 127) * 64;

    const __nv_bfloat16* wth = g_wth + (size_t)mat * DIM * HD;
    const __nv_bfloat16* wtl = g_wtl + (size_t)mat * DIM * HD;

    // stage = 3072 x 16B chunks: A 1024 (Ah 512, Al 512), B 2048 (Bh, Bl)
    auto load_stage = [&](int chunk, int stage) {
        const int k0 = chunk * PJ_BK;
        const uint32_t st = sb + stage * PJ_STAGE_B;
#pragma unroll
        for (int t0 = 0; t0 < 12; t0++) {
            int t = tid + t0 * 256;
            const __nv_bfloat16* src;
            uint32_t dst;
            if (t < 1024) {
                int rr = (t & 511) >> 3, c = t & 7;
                const __nv_bfloat16* base = (t < 512) ? g_xh : g_xl;
                src = base + (size_t)(m0 + rr) * DIM + k0 + c * 8;
                dst = st + ((t < 512) ? PJ_AH : PJ_AL) + rr * PJ_PITCH_B + c * 16;
            } else {
                int t2 = t - 1024;
                int rr = (t2 & 1023) >> 3, c = t2 & 7;
                const __nv_bfloat16* base = (t2 < 1024) ? wth : wtl;
                src = base + (size_t)rr * DIM + k0 + c * 8;
                dst = st + ((t2 < 1024) ? PJ_BH : PJ_BL) + rr * PJ_PITCH_B + c * 16;
            }
            CP_ASYNC16(dst, src);
        }
        CP_COMMIT();
    };

    float acc[2][4][4];
#pragma unroll
    for (int mt = 0; mt < 2; mt++)
#pragma unroll
        for (int nt = 0; nt < 4; nt++)
#pragma unroll
            for (int j = 0; j < 4; j++) acc[mt][nt][j] = 0.f;

    load_stage(0, 0);
    load_stage(1, 1);

    const int gr = lane >> 2;
    const int qo = lane & 3;

    for (int i = 0; i < PJ_NC; i++) {
        if (i < PJ_NC - 1) CP_WAIT1(); else CP_WAIT0();
        __syncthreads();

        const uint32_t* Ah = (const uint32_t*)(smem + (i & 1) * PJ_STAGE_B + PJ_AH);
        const uint32_t* Al = (const uint32_t*)(smem + (i & 1) * PJ_STAGE_B + PJ_AL);
        const uint32_t* Bh = (const uint32_t*)(smem + (i & 1) * PJ_STAGE_B + PJ_BH);
        const uint32_t* Bl = (const uint32_t*)(smem + (i & 1) * PJ_STAGE_B + PJ_BL);

#pragma unroll
        for (int kk = 0; kk < 4; kk++) {
            const int ku = kk * 8 + qo;
            uint32_t ah[2][4], al[2][4], bh[4][2], bl[4][2];
#pragma unroll
            for (int mt = 0; mt < 2; mt++) {
                int r0 = (wm * 32 + mt * 16 + gr) * PJ_PITCH_U;
                int r8 = r0 + 8 * PJ_PITCH_U;
                ah[mt][0] = Ah[r0 + ku];      ah[mt][1] = Ah[r8 + ku];
                ah[mt][2] = Ah[r0 + ku + 4];  ah[mt][3] = Ah[r8 + ku + 4];
                al[mt][0] = Al[r0 + ku];      al[mt][1] = Al[r8 + ku];
                al[mt][2] = Al[r0 + ku + 4];  al[mt][3] = Al[r8 + ku + 4];
            }
#pragma unroll
            for (int nt = 0; nt < 4; nt++) {
                int rn = (wn * 32 + nt * 8 + gr) * PJ_PITCH_U;
                bh[nt][0] = Bh[rn + ku];  bh[nt][1] = Bh[rn + ku + 4];
                bl[nt][0] = Bl[rn + ku];  bl[nt][1] = Bl[rn + ku + 4];
            }
#pragma unroll
            for (int mt = 0; mt < 2; mt++)
#pragma unroll
                for (int nt = 0; nt < 4; nt++)
                    mma_bf16(acc[mt][nt][0], acc[mt][nt][1], acc[mt][nt][2], acc[mt][nt][3],
                             ah[mt][0], ah[mt][1], ah[mt][2], ah[mt][3],
                             bh[nt][0], bh[nt][1]);
#pragma unroll
            for (int mt = 0; mt < 2; mt++)
#pragma unroll
                for (int nt = 0; nt < 4; nt++)
                    mma_bf16(acc[mt][nt][0], acc[mt][nt][1], acc[mt][nt][2], acc[mt][nt][3],
                             ah[mt][0], ah[mt][1], ah[mt][2], ah[mt][3],
                             bl[nt][0], bl[nt][1]);
#pragma unroll
            for (int mt = 0; mt < 2; mt++)
#pragma unroll
                for (int nt = 0; nt < 4; nt++)
                    mma_bf16(acc[mt][nt][0], acc[mt][nt][1], acc[mt][nt][2], acc[mt][nt][3],
                             al[mt][0], al[mt][1], al[mt][2], al[mt][3],
                             bh[nt][0], bh[nt][1]);
        }
        __syncthreads();
        if (i + 2 < PJ_NC) load_stage(i + 2, (i & 1));
    }

    // ---- epilogue ----
    if (mat < 2) {
        __nv_bfloat16* oh = (mat == 0) ? g_qh : g_kh;
        __nv_bfloat16* ol = (mat == 0) ? g_ql : g_kl;
#pragma unroll
        for (int mt = 0; mt < 2; mt++) {
            int row = m0 + wm * 32 + mt * 16 + gr;
#pragma unroll
            for (int nt = 0; nt < 4; nt++) {
                int col = wn * 32 + nt * 8 + 2 * qo;
                uint32_t h01, l01, h23, l23;
                split_pack(acc[mt][nt][0], acc[mt][nt][1], h01, l01);
                split_pack(acc[mt][nt][2], acc[mt][nt][3], h23, l23);
                *(uint32_t*)&oh[(size_t)row * HD + col]       = h01;
                *(uint32_t*)&ol[(size_t)row * HD + col]       = l01;
                *(uint32_t*)&oh[(size_t)(row + 8) * HD + col] = h23;
                *(uint32_t*)&ol[(size_t)(row + 8) * HD + col] = l23;
            }
        }
    } else {
        const int bb = m0 >> 11;
        const int s0 = m0 & 2047;
#pragma unroll
        for (int mt = 0; mt < 2; mt++) {
            int srow = s0 + wm * 32 + mt * 16 + gr;
#pragma unroll
            for (int nt = 0; nt < 4; nt++) {
                int col = wn * 32 + nt * 8 + 2 * qo;
                size_t base = ((size_t)bb * HD + col) * SEQ;
#pragma unroll
                for (int j = 0; j < 4; j++) {
                    float v = acc[mt][nt][j];
                    size_t idx = base + ((j & 1) ? SEQ : 0) + srow + ((j >> 1) * 8);
                    __nv_bfloat16 h = __float2bfloat16(v);
                    g_vth[idx] = h;
                    g_vtl[idx] = __float2bfloat16(v - __bfloat162float(h));
                }
            }
        }
    }
}

// ===========================================================================
// Kernel 2: balanced tensor-core causal flash attention, 8 warps, BQ=128.
// 148 blocks over flat (q-tile, kv-chunk) ranges; BK=64 double-buffered.
// Tile p (q rows [128p,128p+128)) has 2p+2 chunks; f0(p) = p^2+p.
// ===========================================================================
#define FA_SQH   0
#define FA_SQL   34816                 // 128*272
#define FA_STG   69632
#define FA_KH    0
#define FA_KL    17408
#define FA_VTH   34816
#define FA_VTL   53248
#define FA_STGSZ 71680
#define FA_SMEM  (FA_STG + 2 * FA_STGSZ)   // 212992

__global__ void __launch_bounds__(256, 1)
flash_tc_kernel(float* __restrict__ out)
{
    extern __shared__ __align__(16) char smem[];
    const uint32_t sb = smem_u32(smem);
    const int tid  = threadIdx.x;
    const int lane = tid & 31;
    const int warp = tid >> 5;          // 0..7
    const int gr   = lane >> 2;
    const int qo   = lane & 3;
    const int b    = blockIdx.x / FA_BLKS_PB;
    const int j    = blockIdx.x % FA_BLKS_PB;
    const int s_f  = fa_S(j);
    const int e_f  = fa_S(j + 1);

    auto load_stage = [&](int c, int stage) {
        const int k0 = c * 64;
        const uint32_t st = sb + FA_STG + stage * FA_STGSZ;
        const size_t krow0 = (size_t)(b * SEQ + k0) * HD;
        const size_t vrow0 = (size_t)b * HD * SEQ + k0;
#pragma unroll
        for (int t0 = 0; t0 < 16; t0++) {
            int t = tid + t0 * 256;
            int region = t >> 10, sub = t & 1023;
            const __nv_bfloat16* src;
            uint32_t dst;
            if (region < 2) {
                int r = sub >> 4, cc = sub & 15;
                src = ((region == 0) ? g_kh : g_kl) + krow0 + (size_t)r * HD + cc * 8;
                dst = st + ((region == 0) ? FA_KH : FA_KL) + r * 272 + cc * 16;
            } else {
                int r = sub >> 3, cc = sub & 7;
                src = ((region == 2) ? g_vth : g_vtl) + vrow0 + (size_t)r * SEQ + cc * 8;
                dst = st + ((region == 2) ? FA_VTH : FA_VTL) + r * 144 + cc * 16;
            }
            CP_ASYNC16(dst, src);
        }
        CP_COMMIT();
    };

    const int r0 = (16 * warp + gr) * 68;
    const int r8 = r0 + 8 * 68;
    const uint32_t* QH = (const uint32_t*)(smem + FA_SQH);
    const uint32_t* QL = (const uint32_t*)(smem + FA_SQL);

    int f = s_f;
    while (f < e_f) {
        // decode tile p: span [p^2+p, p^2+3p+2)
        int p = (int)((sqrtf(4.f * (float)f + 1.f) - 1.f) * 0.5f);
        while (p * p + 3 * p + 2 <= f) p++;
        while (p * p + p > f) p--;
        const int f0     = p * p + p;
        const int nch    = 2 * p + 2;
        const int cstart = f - f0;
        const int cend   = min(nch, e_f - f0);
        const int q0     = p * 128;

        __syncthreads();   // protect smem reuse across tiles

        load_stage(cstart, 0);
        if (cstart + 1 < cend) load_stage(cstart + 1, 1);
        // Q tile: 128 rows x 16 x 16B per region (hi, lo)
        for (int t = tid; t < 4096; t += 256) {
            int m = t >> 11, r = (t >> 4) & 127, c = t & 15;
            const __nv_bfloat16* src =
                ((m == 0) ? g_qh : g_ql) + (size_t)(b * SEQ + q0 + r) * HD + c * 8;
            float4 v = *(const float4*)src;
            *(float4*)(smem + ((m == 0) ? FA_SQH : FA_SQL) + r * 272 + c * 16) = v;
        }

        float o[16][4];
#pragma unroll
        for (int nt = 0; nt < 16; nt++)
#pragma unroll
            for (int jj = 0; jj < 4; jj++) o[nt][jj] = 0.f;
        float mr0 = -1e30f, mr1 = -1e30f, l0 = 0.f, l1 = 0.f;

        for (int c = cstart; c < cend; c++) {
            if (c + 1 < cend) CP_WAIT1(); else CP_WAIT0();
            __syncthreads();

            const char* st = smem + FA_STG + ((c - cstart) & 1) * FA_STGSZ;
            const uint32_t* KH = (const uint32_t*)(st + FA_KH);
            const uint32_t* KL = (const uint32_t*)(st + FA_KL);
            const uint32_t* VH = (const uint32_t*)(st + FA_VTH);
            const uint32_t* VL = (const uint32_t*)(st + FA_VTL);

            // ---- S = Q K^T ----
            float s[8][4];
#pragma unroll
            for (int nt = 0; nt < 8; nt++)
#pragma unroll
                for (int jj = 0; jj < 4; jj++) s[nt][jj] = 0.f;

#pragma unroll
            for (int kk = 0; kk < 8; kk++) {
                const int ku = kk * 8 + qo;
                uint32_t ah0 = QH[r0 + ku], ah1 = QH[r8 + ku];
                uint32_t ah2 = QH[r0 + ku + 4], ah3 = QH[r8 + ku + 4];
                uint32_t al0 = QL[r0 + ku], al1 = QL[r8 + ku];
                uint32_t al2 = QL[r0 + ku + 4], al3 = QL[r8 + ku + 4];
#pragma unroll
                for (int g = 0; g < 2; g++) {
                    uint32_t bh[4][2], bl[4][2];
#pragma unroll
                    for (int t = 0; t < 4; t++) {
                        int rn = (8 * (4 * g + t) + gr) * 68;
                        bh[t][0] = KH[rn + ku];  bh[t][1] = KH[rn + ku + 4];
                        bl[t][0] = KL[rn + ku];  bl[t][1] = KL[rn + ku + 4];
                    }
#pragma unroll
                    for (int t = 0; t < 4; t++) {
                        int nt = 4 * g + t;
                        mma_bf16(s[nt][0], s[nt][1], s[nt][2], s[nt][3],
                                 ah0, ah1, ah2, ah3, bh[t][0], bh[t][1]);
                    }
#pragma unroll
                    for (int t = 0; t < 4; t++) {
                        int nt = 4 * g + t;
                        mma_bf16(s[nt][0], s[nt][1], s[nt][2], s[nt][3],
                                 ah0, ah1, ah2, ah3, bl[t][0], bl[t][1]);
                    }
#pragma unroll
                    for (int t = 0; t < 4; t++) {
                        int nt = 4 * g + t;
                        mma_bf16(s[nt][0], s[nt][1], s[nt][2], s[nt][3],
                                 al0, al1, al2, al3, bh[t][0], bh[t][1]);
                    }
                }
            }

#pragma unroll
            for (int nt = 0; nt < 8; nt++)
#pragma unroll
                for (int jj = 0; jj < 4; jj++) s[nt][jj] *= SOFTMAX_SCALE;

            if (c >= 2 * p) {   // diagonal-region chunks need masking
                const int qr0 = q0 + 16 * warp + gr;
                const int qr1 = qr0 + 8;
                const int k0v = c * 64;
#pragma unroll
                for (int nt = 0; nt < 8; nt++) {
                    int c0 = k0v + 8 * nt + 2 * qo, c1 = c0 + 1;
                    if (c0 > qr0) s[nt][0] = -1e30f;
                    if (c1 > qr0) s[nt][1] = -1e30f;
                    if (c0 > qr1) s[nt][2] = -1e30f;
                    if (c1 > qr1) s[nt][3] = -1e30f;
                }
            }

            // ---- online softmax (warp-local) ----
            float mx0 = -1e30f, mx1 = -1e30f;
#pragma unroll
            for (int nt = 0; nt < 8; nt++) {
                mx0 = fmaxf(mx0, fmaxf(s[nt][0], s[nt][1]));
                mx1 = fmaxf(mx1, fmaxf(s[nt][2], s[nt][3]));
            }
            mx0 = fmaxf(mx0, __shfl_xor_sync(0xffffffffu, mx0, 1));
            mx0 = fmaxf(mx0, __shfl_xor_sync(0xffffffffu, mx0, 2));
            mx1 = fmaxf(mx1, __shfl_xor_sync(0xffffffffu, mx1, 1));
            mx1 = fmaxf(mx1, __shfl_xor_sync(0xffffffffu, mx1, 2));
            float mn0 = fmaxf(mr0, mx0), mn1 = fmaxf(mr1, mx1);
            float corr0 = __expf(mr0 - mn0), corr1 = __expf(mr1 - mn1);
            mr0 = mn0; mr1 = mn1;

            float ls0 = 0.f, ls1 = 0.f;
#pragma unroll
            for (int nt = 0; nt < 8; nt++) {
                s[nt][0] = __expf(s[nt][0] - mn0); ls0 += s[nt][0];
                s[nt][1] = __expf(s[nt][1] - mn0); ls0 += s[nt][1];
                s[nt][2] = __expf(s[nt][2] - mn1); ls1 += s[nt][2];
                s[nt][3] = __expf(s[nt][3] - mn1); ls1 += s[nt][3];
            }
            ls0 += __shfl_xor_sync(0xffffffffu, ls0, 1);
            ls0 += __shfl_xor_sync(0xffffffffu, ls0, 2);
            ls1 += __shfl_xor_sync(0xffffffffu, ls1, 1);
            ls1 += __shfl_xor_sync(0xffffffffu, ls1, 2);
            l0 = l0 * corr0 + ls0;
            l1 = l1 * corr1 + ls1;

#pragma unroll
            for (int nt = 0; nt < 16; nt++) {
                o[nt][0] *= corr0; o[nt][1] *= corr0;
                o[nt][2] *= corr1; o[nt][3] *= corr1;
            }

            // ---- O += P V ----
#pragma unroll
            for (int kp = 0; kp < 4; kp++) {
                const int t0 = 2 * kp, t1 = 2 * kp + 1;
                uint32_t ah0, al0, ah1, al1, ah2, al2, ah3, al3;
                split_pack(s[t0][0], s[t0][1], ah0, al0);
                split_pack(s[t0][2], s[t0][3], ah1, al1);
                split_pack(s[t1][0], s[t1][1], ah2, al2);
                split_pack(s[t1][2], s[t1][3], ah3, al3);
                const int ku = 8 * kp + qo;
#pragma unroll
                for (int g = 0; g < 4; g++) {
                    uint32_t vh[4][2], vl[4][2];
#pragma unroll
                    for (int t = 0; t < 4; t++) {
                        int rn = (8 * (4 * g + t) + gr) * 36;
                        vh[t][0] = VH[rn + ku];  vh[t][1] = VH[rn + ku + 4];
                        vl[t][0] = VL[rn + ku];  vl[t][1] = VL[rn + ku + 4];
                    }
#pragma unroll
                    for (int t = 0; t < 4; t++) {
                        int nt = 4 * g + t;
                        mma_bf16(o[nt][0], o[nt][1], o[nt][2], o[nt][3],
                                 ah0, ah1, ah2, ah3, vh[t][0], vh[t][1]);
                    }
#pragma unroll
                    for (int t = 0; t < 4; t++) {
                        int nt = 4 * g + t;
                        mma_bf16(o[nt][0], o[nt][1], o[nt][2], o[nt][3],
                                 ah0, ah1, ah2, ah3, vl[t][0], vl[t][1]);
                    }
#pragma unroll
                    for (int t = 0; t < 4; t++) {
                        int nt = 4 * g + t;
                        mma_bf16(o[nt][0], o[nt][1], o[nt][2], o[nt][3],
                                 al0, al1, al2, al3, vh[t][0], vh[t][1]);
                    }
                }
            }

            __syncthreads();
            if (c + 2 < cend) load_stage(c + 2, (c - cstart) & 1);
        } // chunks

        // ---- tile epilogue ----
        const int row0 = 16 * warp + gr;
        if (cstart == 0 && cend == nch) {
            const float inv0 = 1.0f / l0;
            const float inv1 = 1.0f / l1;
            float* og  = out + ((size_t)b * SEQ + q0 + row0) * HD;
            float* og8 = og + 8 * HD;
#pragma unroll
            for (int nt = 0; nt < 16; nt++) {
                int cc = 8 * nt + 2 * qo;
                *(float2*)&og[cc]  = make_float2(o[nt][0] * inv0, o[nt][1] * inv0);
                *(float2*)&og8[cc] = make_float2(o[nt][2] * inv1, o[nt][3] * inv1);
            }
        } else {
            const int slot = j - fa_block_of(f0);
            const size_t base = ((size_t)(b * FA_TILES + p)) * FA_MAXSLOT + slot;
            if (qo == 0) {
                g_pm[base * 128 + row0]     = mr0;
                g_pl[base * 128 + row0]     = l0;
                g_pm[base * 128 + row0 + 8] = mr1;
                g_pl[base * 128 + row0 + 8] = l1;
            }
            float* po  = g_po + (base * 128 + row0) * 128;
            float* po8 = po + 8 * 128;
#pragma unroll
            for (int nt = 0; nt < 16; nt++) {
                int cc = 8 * nt + 2 * qo;
                *(float2*)&po[cc]  = make_float2(o[nt][0], o[nt][1]);
                *(float2*)&po8[cc] = make_float2(o[nt][2], o[nt][3]);
            }
        }

        f = f0 + cend;
    } // tiles
}

// ===========================================================================
// Kernel 3: combine split-KV partials. grid = BATCH*FA_TILES, 128 threads.
// ===========================================================================
__global__ void fa_combine_kernel(float* __restrict__ out)
{
    const int p = blockIdx.x & (FA_TILES - 1);
    const int b = blockIdx.x >> 4;
    const int f0 = p * p + p;
    const int j0 = fa_block_of(f0);
    const int j1 = fa_block_of(f0 + 2 * p + 1);
    if (j0 == j1) return;                    // single block wrote final
    const int ns = j1 - j0 + 1;
    const int r  = threadIdx.x;              // 0..127

    const size_t base = ((size_t)(b * FA_TILES + p)) * FA_MAXSLOT;
    float m = -1e30f;
    for (int i = 0; i < ns; i++) m = fmaxf(m, g_pm[(base + i) * 128 + r]);
    float w[FA_MAXSLOT];
    float l = 0.f;
    for (int i = 0; i < ns; i++) {
        w[i] = __expf(g_pm[(base + i) * 128 + r] - m);
        l += g_pl[(base + i) * 128 + r] * w[i];
    }
    const float inv = 1.0f / l;

    float* og = out + ((size_t)b * SEQ + p * 128 + r) * HD;
    for (int c = 0; c < HD; c += 4) {
        float4 acc = make_float4(0.f, 0.f, 0.f, 0.f);
        for (int i = 0; i < ns; i++) {
            const float4 v = *(const float4*)&g_po[((base + i) * 128 + r) * 128 + c];
            acc.x += v.x * w[i]; acc.y += v.y * w[i];
            acc.z += v.z * w[i]; acc.w += v.w * w[i];
        }
        *(float4*)&og[c] = make_float4(acc.x * inv, acc.y * inv,
                                       acc.z * inv, acc.w * inv);
    }
}

// ===========================================================================
// Launcher
// ===========================================================================
extern "C" void kernel_launch(void* const* d_in, const int* in_sizes, int n_in,
                              void* d_out, int out_size)
{
    const float* x = nullptr;
    const float* W[3] = {nullptr, nullptr, nullptr};
    int wn = 0;
    for (int i = 0; i < n_in; i++) {
        if (in_sizes[i] == BATCH * SEQ * DIM) {
            x = (const float*)d_in[i];
        } else if (in_sizes[i] == DIM * HD && wn < 3) {
            W[wn++] = (const float*)d_in[i];
        }
    }
    float* out = (float*)d_out;

    cudaFuncSetAttribute(qkv_mma_kernel,
                         cudaFuncAttributeMaxDynamicSharedMemorySize, PJ_SMEM);
    cudaFuncSetAttribute(flash_tc_kernel,
                         cudaFuncAttributeMaxDynamicSharedMemorySize, FA_SMEM);

    convert_x_kernel<<<1024, 256>>>(x);
    convert_w_kernel<<<dim3(512, 3), 256>>>(W[0], W[1], W[2]);
    qkv_mma_kernel<<<384, 256, PJ_SMEM>>>();
    flash_tc_kernel<<<FA_BLKS, 256, FA_SMEM>>>(out);
    fa_combine_kernel<<<BATCH * FA_TILES, 128>>>(out);
}